// round 1
// baseline (speedup 1.0000x reference)
#include <cuda_runtime.h>
#include <cstddef>

// ----------------------------------------------------------------------------
// Decoder step: Bahdanau attention + GRU cell + fc, B=128, S=1024, U=1024.
//
// Inputs (metadata order):
//  0 x        (128,1,64)       1 hidden (128,1024)     2 enc_output (128,1024,1024)
//  3 W1 (1024,1024)  4 b1 (1024)  5 W2 (1024,1024)  6 b2 (1024)
//  7 V  (1024,1)     8 bV (1)
//  9 Wk (1088,3072) 10 Wr (1024,3072) 11 bg (3072)
// 12 Wfc (1024,64)  13 bfc (64)
//
// Output buffer (270336 f32): [ out (128*64) | state (128*1024) | attn (128*1024) ]
// ----------------------------------------------------------------------------

#define BATCH   128
#define SEQ     1024
#define UNITS   1024
#define INDIM   64
#define GINLEN  (UNITS + INDIM)   // 1088
#define G3U     (3 * UNITS)       // 3072

// ---------------- scratch (no allocations allowed) ----------------
__device__ __align__(16) float g_q     [BATCH * UNITS];   // hidden@W2 + b2
__device__ __align__(16) float g_scores[BATCH * SEQ];
__device__ __align__(16) float g_gin   [BATCH * GINLEN];  // [context | x]
__device__ __align__(16) float g_xg    [BATCH * G3U];
__device__ __align__(16) float g_hwr   [BATCH * G3U];
__device__ __align__(16) float g_z     [BATCH * UNITS];
__device__ __align__(16) float g_rh    [BATCH * UNITS];
__device__ __align__(16) float g_rhwr  [BATCH * UNITS];
__device__ __align__(16) float g_state [BATCH * UNITS];

// ----------------------------------------------------------------------------
// Generic small SGEMM with optional bias: C[M=128, N] = A[128,K] @ B[K,N] + bias
// Block tile 128x64, K-step 16, thread tile 8x4, 256 threads.
// Requires: M == 128, K % 16 == 0, N % 64 == 0, lda/ldb % 4 == 0, 16B-aligned ptrs.
// ----------------------------------------------------------------------------
__global__ __launch_bounds__(256)
void sgemm_bias_kernel(const float* __restrict__ A, int lda,
                       const float* __restrict__ B, int ldb,
                       float* __restrict__ C, int ldc,
                       const float* __restrict__ bias,
                       int K)
{
    __shared__ float As[16][128 + 4];
    __shared__ float Bs[16][64];

    const int tid = threadIdx.x;
    const int n0  = blockIdx.x * 64;
    const int tm  = (tid >> 4) * 8;   // 0..120
    const int tn  = (tid & 15) * 4;   // 0..60

    float acc[8][4];
    #pragma unroll
    for (int i = 0; i < 8; i++)
        #pragma unroll
        for (int j = 0; j < 4; j++) acc[i][j] = 0.f;

    for (int kk = 0; kk < K; kk += 16) {
        // A tile 128x16, transposed into As
        #pragma unroll
        for (int it = 0; it < 2; it++) {
            int t4  = it * 256 + tid;
            int row = t4 >> 2;
            int col = (t4 & 3) * 4;
            float4 v = *reinterpret_cast<const float4*>(&A[(size_t)row * lda + kk + col]);
            As[col + 0][row] = v.x;
            As[col + 1][row] = v.y;
            As[col + 2][row] = v.z;
            As[col + 3][row] = v.w;
        }
        // B tile 16x64
        {
            int row = tid >> 4;
            int c4  = (tid & 15) * 4;
            *reinterpret_cast<float4*>(&Bs[row][c4]) =
                *reinterpret_cast<const float4*>(&B[(size_t)(kk + row) * ldb + n0 + c4]);
        }
        __syncthreads();

        #pragma unroll
        for (int k = 0; k < 16; k++) {
            float ra[8], rb[4];
            *reinterpret_cast<float4*>(&ra[0]) = *reinterpret_cast<const float4*>(&As[k][tm]);
            *reinterpret_cast<float4*>(&ra[4]) = *reinterpret_cast<const float4*>(&As[k][tm + 4]);
            *reinterpret_cast<float4*>(&rb[0]) = *reinterpret_cast<const float4*>(&Bs[k][tn]);
            #pragma unroll
            for (int i = 0; i < 8; i++)
                #pragma unroll
                for (int j = 0; j < 4; j++)
                    acc[i][j] += ra[i] * rb[j];
        }
        __syncthreads();
    }

    #pragma unroll
    for (int j = 0; j < 4; j++) {
        float bv = bias ? bias[n0 + tn + j] : 0.f;
        #pragma unroll
        for (int i = 0; i < 8; i++)
            C[(size_t)(tm + i) * ldc + n0 + tn + j] = acc[i][j] + bv;
    }
}

// ----------------------------------------------------------------------------
// Fused score kernel: for one (b, s-tile of 128):
//   scores[b,s] = bV + sum_n V[n] * tanh( enc[b,s,:]@W1[:,n] + b1[n] + q[b,n] )
// 128x128x16 register-tiled fp32 GEMM, n looped in tiles of 128 inside the CTA,
// epilogue reduces over n into shared score accumulators.
// ----------------------------------------------------------------------------
__global__ __launch_bounds__(256)
void score_kernel(const float* __restrict__ enc,
                  const float* __restrict__ W1,
                  const float* __restrict__ b1,
                  const float* __restrict__ V,
                  const float* __restrict__ bV)
{
    __shared__ float As[16][128 + 4];
    __shared__ float Bs[16][128];
    __shared__ float sacc[128];

    const int tid = threadIdx.x;
    const int b   = blockIdx.y;
    const int s0  = blockIdx.x * 128;
    const float* Ab = enc + ((size_t)b * SEQ + s0) * UNITS;

    if (tid < 128) sacc[tid] = 0.f;

    const int tm = (tid >> 4) * 8;   // s within tile
    const int tn = (tid & 15) * 8;   // n within tile

    for (int n0 = 0; n0 < UNITS; n0 += 128) {
        float acc[8][8];
        #pragma unroll
        for (int i = 0; i < 8; i++)
            #pragma unroll
            for (int j = 0; j < 8; j++) acc[i][j] = 0.f;

        for (int kk = 0; kk < UNITS; kk += 16) {
            // enc tile 128x16 -> transposed
            #pragma unroll
            for (int it = 0; it < 2; it++) {
                int t4  = it * 256 + tid;
                int row = t4 >> 2;
                int col = (t4 & 3) * 4;
                float4 v = *reinterpret_cast<const float4*>(&Ab[(size_t)row * UNITS + kk + col]);
                As[col + 0][row] = v.x;
                As[col + 1][row] = v.y;
                As[col + 2][row] = v.z;
                As[col + 3][row] = v.w;
            }
            // W1 tile 16x128
            #pragma unroll
            for (int it = 0; it < 2; it++) {
                int t4  = it * 256 + tid;
                int row = t4 >> 5;
                int c4  = (t4 & 31) * 4;
                *reinterpret_cast<float4*>(&Bs[row][c4]) =
                    *reinterpret_cast<const float4*>(&W1[(size_t)(kk + row) * UNITS + n0 + c4]);
            }
            __syncthreads();

            #pragma unroll
            for (int k = 0; k < 16; k++) {
                float ra[8], rb[8];
                *reinterpret_cast<float4*>(&ra[0]) = *reinterpret_cast<const float4*>(&As[k][tm]);
                *reinterpret_cast<float4*>(&ra[4]) = *reinterpret_cast<const float4*>(&As[k][tm + 4]);
                *reinterpret_cast<float4*>(&rb[0]) = *reinterpret_cast<const float4*>(&Bs[k][tn]);
                *reinterpret_cast<float4*>(&rb[4]) = *reinterpret_cast<const float4*>(&Bs[k][tn + 4]);
                #pragma unroll
                for (int i = 0; i < 8; i++)
                    #pragma unroll
                    for (int j = 0; j < 8; j++)
                        acc[i][j] += ra[i] * rb[j];
            }
            __syncthreads();
        }

        // epilogue: part[s] += sum_j V[n] * tanh(acc + q[b,n] + b1[n])
        float part[8];
        #pragma unroll
        for (int i = 0; i < 8; i++) part[i] = 0.f;
        #pragma unroll
        for (int j = 0; j < 8; j++) {
            int n = n0 + tn + j;
            float qv = g_q[(size_t)b * UNITS + n] + b1[n];
            float vv = V[n];
            #pragma unroll
            for (int i = 0; i < 8; i++)
                part[i] += vv * tanhf(acc[i][j] + qv);
        }
        #pragma unroll
        for (int i = 0; i < 8; i++)
            atomicAdd(&sacc[tm + i], part[i]);
        __syncthreads();
    }

    if (tid < 128)
        g_scores[(size_t)b * SEQ + s0 + tid] = sacc[tid] + bV[0];
}

// ----------------------------------------------------------------------------
// Softmax over S per batch row, writes attention weights into d_out attn slab.
// ----------------------------------------------------------------------------
__global__ __launch_bounds__(256)
void softmax_kernel(float* __restrict__ out_attn)
{
    __shared__ float sh[SEQ];
    __shared__ float red[256];
    const int b   = blockIdx.x;
    const int tid = threadIdx.x;

    float m = -1e30f;
    for (int i = tid; i < SEQ; i += 256) {
        float v = g_scores[(size_t)b * SEQ + i];
        sh[i] = v;
        m = fmaxf(m, v);
    }
    red[tid] = m;
    __syncthreads();
    for (int s = 128; s > 0; s >>= 1) {
        if (tid < s) red[tid] = fmaxf(red[tid], red[tid + s]);
        __syncthreads();
    }
    m = red[0];
    __syncthreads();

    float sum = 0.f;
    for (int i = tid; i < SEQ; i += 256) {
        float e = expf(sh[i] - m);
        sh[i] = e;
        sum += e;
    }
    red[tid] = sum;
    __syncthreads();
    for (int s = 128; s > 0; s >>= 1) {
        if (tid < s) red[tid] += red[tid + s];
        __syncthreads();
    }
    float inv = 1.f / red[0];
    for (int i = tid; i < SEQ; i += 256)
        out_attn[(size_t)b * SEQ + i] = sh[i] * inv;
}

// ----------------------------------------------------------------------------
// context[b,u] = sum_s attn[b,s] * enc[b,s,u]  -> writes into g_gin[:, 0:1024]
// ----------------------------------------------------------------------------
__global__ __launch_bounds__(256)
void context_kernel(const float* __restrict__ enc,
                    const float* __restrict__ attn)
{
    __shared__ float w[SEQ];
    const int b   = blockIdx.y;
    const int u0  = blockIdx.x * 256;
    const int tid = threadIdx.x;

    for (int i = tid; i < SEQ; i += 256)
        w[i] = attn[(size_t)b * SEQ + i];
    __syncthreads();

    const float* e = enc + (size_t)b * SEQ * UNITS + u0 + tid;
    float acc = 0.f;
    #pragma unroll 8
    for (int s = 0; s < SEQ; s++)
        acc += w[s] * e[(size_t)s * UNITS];

    g_gin[(size_t)b * GINLEN + u0 + tid] = acc;
}

// copy x into g_gin[:, 1024:1088]
__global__ void copyx_kernel(const float* __restrict__ x)
{
    int i = blockIdx.x * 256 + threadIdx.x;
    if (i < BATCH * INDIM) {
        int b = i >> 6, u = i & 63;
        g_gin[(size_t)b * GINLEN + UNITS + u] = x[i];
    }
}

// z, r gates + r*hidden
__global__ __launch_bounds__(256)
void gates_kernel(const float* __restrict__ hidden)
{
    int i = blockIdx.x * 256 + threadIdx.x;   // 0 .. 131071
    int b = i >> 10, u = i & 1023;
    size_t base = (size_t)b * G3U;
    float z = 1.f / (1.f + expf(-(g_xg[base + u]          + g_hwr[base + u])));
    float r = 1.f / (1.f + expf(-(g_xg[base + UNITS + u]  + g_hwr[base + UNITS + u])));
    g_z[i]  = z;
    g_rh[i] = r * hidden[i];
}

// state = z*h + (1-z)*tanh(xg_h + (r*h)@Wr_h)
__global__ __launch_bounds__(256)
void state_kernel(const float* __restrict__ hidden, float* __restrict__ out_state)
{
    int i = blockIdx.x * 256 + threadIdx.x;
    int b = i >> 10, u = i & 1023;
    float hh = tanhf(g_xg[(size_t)b * G3U + 2 * UNITS + u] + g_rhwr[i]);
    float z  = g_z[i];
    float st = z * hidden[i] + (1.f - z) * hh;
    out_state[i] = st;
    g_state[i]   = st;
}

// ----------------------------------------------------------------------------
extern "C" void kernel_launch(void* const* d_in, const int* in_sizes, int n_in,
                              void* d_out_v, int out_size)
{
    const float* x      = (const float*)d_in[0];
    const float* hidden = (const float*)d_in[1];
    const float* enc    = (const float*)d_in[2];
    const float* W1     = (const float*)d_in[3];
    const float* b1     = (const float*)d_in[4];
    const float* W2     = (const float*)d_in[5];
    const float* b2     = (const float*)d_in[6];
    const float* V      = (const float*)d_in[7];
    const float* bV     = (const float*)d_in[8];
    const float* Wk     = (const float*)d_in[9];
    const float* Wr     = (const float*)d_in[10];
    const float* bg     = (const float*)d_in[11];
    const float* Wfc    = (const float*)d_in[12];
    const float* bfc    = (const float*)d_in[13];

    float* d_out     = (float*)d_out_v;
    float* out_fc    = d_out;                              // 128*64
    float* out_state = d_out + BATCH * INDIM;              // 128*1024
    float* out_attn  = d_out + BATCH * INDIM + BATCH * UNITS;

    float *q, *gin, *xg, *hwr, *rh, *rhwr, *state;
    cudaGetSymbolAddress((void**)&q,     g_q);
    cudaGetSymbolAddress((void**)&gin,   g_gin);
    cudaGetSymbolAddress((void**)&xg,    g_xg);
    cudaGetSymbolAddress((void**)&hwr,   g_hwr);
    cudaGetSymbolAddress((void**)&rh,    g_rh);
    cudaGetSymbolAddress((void**)&rhwr,  g_rhwr);
    cudaGetSymbolAddress((void**)&state, g_state);

    // 1. q = hidden @ W2 + b2
    sgemm_bias_kernel<<<dim3(UNITS / 64), 256>>>(hidden, UNITS, W2, UNITS, q, UNITS, b2, UNITS);
    // 2. raw attention scores (dominant GEMM, fused tanh/V epilogue)
    score_kernel<<<dim3(SEQ / 128, BATCH), 256>>>(enc, W1, b1, V, bV);
    // 3. softmax -> attention weights (final output slab)
    softmax_kernel<<<BATCH, 256>>>(out_attn);
    // 4. gin = [context | x]
    copyx_kernel<<<(BATCH * INDIM + 255) / 256, 256>>>(x);
    context_kernel<<<dim3(UNITS / 256, BATCH), 256>>>(enc, out_attn);
    // 5. GRU input/recurrent projections
    sgemm_bias_kernel<<<dim3(G3U / 64), 256>>>(gin, GINLEN, Wk, G3U, xg, G3U, bg, GINLEN);
    sgemm_bias_kernel<<<dim3(G3U / 64), 256>>>(hidden, UNITS, Wr, G3U, hwr, G3U, nullptr, UNITS);
    // 6. z, r gates; rh = r*hidden
    gates_kernel<<<(BATCH * UNITS) / 256, 256>>>(hidden);
    // 7. (r*h) @ Wr[:, 2U:3U]
    sgemm_bias_kernel<<<dim3(UNITS / 64), 256>>>(rh, UNITS, Wr + 2 * UNITS, G3U, rhwr, UNITS, nullptr, UNITS);
    // 8. state (output slab 2)
    state_kernel<<<(BATCH * UNITS) / 256, 256>>>(hidden, out_state);
    // 9. out = state @ Wfc + bfc (output slab 1)
    sgemm_bias_kernel<<<dim3(INDIM / 64), 256>>>(state, UNITS, Wfc, INDIM, out_fc, INDIM, bfc, UNITS);
}

// round 3
// speedup vs baseline: 2.1434x; 2.1434x over previous
#include <cuda_runtime.h>
#include <cuda_bf16.h>
#include <cstdint>
#include <cstddef>

// ----------------------------------------------------------------------------
// Decoder step: Bahdanau attention + GRU cell + fc, B=128, S=1024, U=1024.
// Score GEMM (99% of FLOPs) on warp-level mma.sync bf16 (sm_80+ PTX, legal on
// the compute_100 virtual target) with hi/lo split -> ~1e-5 accuracy.
// ----------------------------------------------------------------------------

#define BATCH   128
#define SEQ     1024
#define UNITS   1024
#define INDIM   64
#define GINLEN  (UNITS + INDIM)   // 1088
#define G3U     (3 * UNITS)       // 3072
#define NTILES  8                 // 1024 / 128 n-tiles

// ---------------- scratch (no allocations allowed) ----------------
__device__ __align__(16) __nv_bfloat16 g_enc_hi[(size_t)BATCH * SEQ * UNITS];
__device__ __align__(16) __nv_bfloat16 g_enc_lo[(size_t)BATCH * SEQ * UNITS];
__device__ __align__(16) __nv_bfloat16 g_w1t_hi[(size_t)UNITS * UNITS];   // W1^T
__device__ __align__(16) __nv_bfloat16 g_w1t_lo[(size_t)UNITS * UNITS];
__device__ __align__(16) float g_q     [BATCH * UNITS];
__device__ __align__(16) float g_part  [NTILES * BATCH * SEQ];
__device__ __align__(16) float g_scores[BATCH * SEQ];
__device__ __align__(16) float g_gin   [BATCH * GINLEN];
__device__ __align__(16) float g_xg    [BATCH * G3U];
__device__ __align__(16) float g_hwr   [BATCH * G3U];
__device__ __align__(16) float g_z     [BATCH * UNITS];
__device__ __align__(16) float g_rh    [BATCH * UNITS];
__device__ __align__(16) float g_rhwr  [BATCH * UNITS];
__device__ __align__(16) float g_state [BATCH * UNITS];

// ======================= PTX helpers (all sm_80-era, no 'a' features) ======
__device__ __forceinline__ uint32_t smem_u32(const void* p) {
    uint32_t a;
    asm("{ .reg .u64 t; cvta.to.shared.u64 t, %1; cvt.u32.u64 %0, t; }" : "=r"(a) : "l"(p));
    return a;
}
#define CP_ASYNC16(dst, src) \
    asm volatile("cp.async.cg.shared.global [%0], [%1], 16;" :: "r"(dst), "l"(src))
#define CP_COMMIT() asm volatile("cp.async.commit_group;" ::: "memory")

__device__ __forceinline__ void ldsm_x4(uint32_t r[4], uint32_t addr) {
    asm volatile("ldmatrix.sync.aligned.m8n8.x4.shared.b16 {%0,%1,%2,%3}, [%4];"
                 : "=r"(r[0]), "=r"(r[1]), "=r"(r[2]), "=r"(r[3]) : "r"(addr));
}
__device__ __forceinline__ void ldsm_x2(uint32_t r[2], uint32_t addr) {
    asm volatile("ldmatrix.sync.aligned.m8n8.x2.shared.b16 {%0,%1}, [%2];"
                 : "=r"(r[0]), "=r"(r[1]) : "r"(addr));
}
__device__ __forceinline__ void mma_bf16(float c[4], const uint32_t a[4], const uint32_t b[2]) {
    asm volatile(
        "mma.sync.aligned.m16n8k16.row.col.f32.bf16.bf16.f32 "
        "{%0,%1,%2,%3}, {%4,%5,%6,%7}, {%8,%9}, {%0,%1,%2,%3};"
        : "+f"(c[0]), "+f"(c[1]), "+f"(c[2]), "+f"(c[3])
        : "r"(a[0]), "r"(a[1]), "r"(a[2]), "r"(a[3]), "r"(b[0]), "r"(b[1]));
}

// ======================= precompute kernels =======================
__global__ __launch_bounds__(256)
void split_enc_kernel(const float* __restrict__ enc)
{
    size_t i = ((size_t)blockIdx.x * 256 + threadIdx.x) * 8;
    float4 v0 = *reinterpret_cast<const float4*>(enc + i);
    float4 v1 = *reinterpret_cast<const float4*>(enc + i + 4);
    float x[8] = {v0.x, v0.y, v0.z, v0.w, v1.x, v1.y, v1.z, v1.w};
    union { __nv_bfloat16 h[8]; uint4 u; } hi, lo;
    #pragma unroll
    for (int j = 0; j < 8; j++) {
        __nv_bfloat16 h = __float2bfloat16(x[j]);
        hi.h[j] = h;
        lo.h[j] = __float2bfloat16(x[j] - __bfloat162float(h));
    }
    *reinterpret_cast<uint4*>(g_enc_hi + i) = hi.u;
    *reinterpret_cast<uint4*>(g_enc_lo + i) = lo.u;
}

// W1 [k][n] fp32 -> W1^T [n][k] hi/lo bf16
__global__ __launch_bounds__(256)
void w1_split_kernel(const float* __restrict__ W1)
{
    __shared__ float tile[32][33];
    int n0 = blockIdx.x * 32, k0 = blockIdx.y * 32;
    int tx = threadIdx.x, ty = threadIdx.y;   // 32 x 8
    #pragma unroll
    for (int i = 0; i < 4; i++)
        tile[ty + i * 8][tx] = W1[(size_t)(k0 + ty + i * 8) * UNITS + n0 + tx];
    __syncthreads();
    #pragma unroll
    for (int i = 0; i < 4; i++) {
        float v = tile[tx][ty + i * 8];
        __nv_bfloat16 h = __float2bfloat16(v);
        size_t o = (size_t)(n0 + ty + i * 8) * UNITS + k0 + tx;
        g_w1t_hi[o] = h;
        g_w1t_lo[o] = __float2bfloat16(v - __bfloat162float(h));
    }
}

// ======================= warp-MMA score GEMM =======================
// CTA: (b, s-tile 128, n-tile 128). K = 1024 in 16 chunks of 64.
// smem per stage: 4 tiles (A_hi, A_lo, B_hi, B_lo), 128 rows x 64 bf16,
// padded row stride 144 B (conflict-free ldmatrix). 2 stages.
#define ROWB    144
#define T_AH    0
#define T_AL    (128 * ROWB)
#define T_BH    (2 * 128 * ROWB)
#define T_BL    (3 * 128 * ROWB)
#define STAGE_B (4 * 128 * ROWB)          // 73728
#define SCORE_SMEM (2 * STAGE_B)          // 147456

__device__ __forceinline__ void fill_stage(uint32_t stage,
                                           const char* eh, const char* el,
                                           const char* bh, const char* bl,
                                           int chunk, int tid)
{
    const int kb = chunk * 128;           // 64 bf16 = 128 bytes
    #pragma unroll
    for (int t = 0; t < 4; t++) {         // 1024 (row,chunk16) pairs / 256 thr
        int idx = t * 256 + tid;
        int row = idx >> 3, ch = idx & 7;
        uint32_t so = (uint32_t)(row * ROWB + ch * 16);
        size_t   go = (size_t)row * (UNITS * 2) + kb + ch * 16;
        CP_ASYNC16(stage + T_AH + so, eh + go);
        CP_ASYNC16(stage + T_AL + so, el + go);
        CP_ASYNC16(stage + T_BH + so, bh + go);
        CP_ASYNC16(stage + T_BL + so, bl + go);
    }
}

__global__ __launch_bounds__(256, 1)
void score_mma_kernel(const float* __restrict__ q,
                      const float* __restrict__ b1,
                      const float* __restrict__ V)
{
    extern __shared__ __align__(128) char smem[];
    __shared__ float sacc[128];
    const uint32_t sb = smem_u32(smem);

    const int tid    = threadIdx.x;
    const int lane   = tid & 31;
    const int wid    = tid >> 5;
    const int warp_m = wid >> 2;          // 0..1  (64 rows each)
    const int warp_n = wid & 3;           // 0..3  (32 cols each)
    const int n0     = blockIdx.x * 128;
    const int s0     = blockIdx.y * 128;
    const int b      = blockIdx.z;

    if (tid < 128) sacc[tid] = 0.f;

    const char* eh = (const char*)(g_enc_hi + ((size_t)b * SEQ + s0) * UNITS);
    const char* el = (const char*)(g_enc_lo + ((size_t)b * SEQ + s0) * UNITS);
    const char* bh = (const char*)(g_w1t_hi + (size_t)n0 * UNITS);
    const char* bl = (const char*)(g_w1t_lo + (size_t)n0 * UNITS);

    fill_stage(sb,           eh, el, bh, bl, 0, tid); CP_COMMIT();
    fill_stage(sb + STAGE_B, eh, el, bh, bl, 1, tid); CP_COMMIT();

    float acc[4][4][4];
    #pragma unroll
    for (int mi = 0; mi < 4; mi++)
        #pragma unroll
        for (int ni = 0; ni < 4; ni++)
            #pragma unroll
            for (int c = 0; c < 4; c++) acc[mi][ni][c] = 0.f;

    // ldmatrix lane addressing (fixed per thread)
    const int a_row = (lane & 15);          // + mi*16 + warp_m*64
    const int a_kh  = (lane >> 4) * 16;     // k-half byte offset
    const int b_row = (lane & 7);           // + ni*8 + warp_n*32
    const int b_kh  = ((lane >> 3) & 1) * 16;

    for (int c = 0; c < 16; c++) {
        if (c >= 14) asm volatile("cp.async.wait_group 0;" ::: "memory");
        else         asm volatile("cp.async.wait_group 1;" ::: "memory");
        __syncthreads();

        const uint32_t stage = sb + (uint32_t)(c & 1) * STAGE_B;
        const uint32_t aBase = stage + (warp_m * 64 + a_row) * ROWB + a_kh;
        const uint32_t bBase = stage + T_BH + (warp_n * 32 + b_row) * ROWB + b_kh;

        #pragma unroll
        for (int k16 = 0; k16 < 4; k16++) {
            const uint32_t kb2 = k16 * 32;
            uint32_t ah[4][4], al[4][4];
            #pragma unroll
            for (int mi = 0; mi < 4; mi++) {
                ldsm_x4(ah[mi], aBase + T_AH + mi * (16 * ROWB) + kb2);
                ldsm_x4(al[mi], aBase + T_AL + mi * (16 * ROWB) + kb2);
            }
            #pragma unroll
            for (int ni = 0; ni < 4; ni++) {
                uint32_t bhf[2], blf[2];
                ldsm_x2(bhf, bBase + ni * (8 * ROWB) + kb2);
                ldsm_x2(blf, bBase + (T_BL - T_BH) + ni * (8 * ROWB) + kb2);
                #pragma unroll
                for (int mi = 0; mi < 4; mi++) {
                    mma_bf16(acc[mi][ni], ah[mi], bhf);
                    mma_bf16(acc[mi][ni], al[mi], bhf);
                    mma_bf16(acc[mi][ni], ah[mi], blf);
                }
            }
        }
        __syncthreads();
        if (c + 2 < 16) {
            fill_stage(stage, eh, el, bh, bl, c + 2, tid);
            CP_COMMIT();
        }
    }

    // Epilogue: part[s] = sum_n V[n]*tanh(acc + q[b,n] + b1[n])
    const size_t qb = (size_t)b * UNITS;
    #pragma unroll
    for (int mi = 0; mi < 4; mi++) {
        float p0 = 0.f, p1 = 0.f;
        const int r = warp_m * 64 + mi * 16 + (lane >> 2);
        #pragma unroll
        for (int ni = 0; ni < 4; ni++) {
            #pragma unroll
            for (int cc = 0; cc < 4; cc++) {
                int n = n0 + warp_n * 32 + ni * 8 + (lane & 3) * 2 + (cc & 1);
                float t = V[n] * tanhf(acc[mi][ni][cc] + q[qb + n] + b1[n]);
                if (cc < 2) p0 += t; else p1 += t;
            }
        }
        p0 += __shfl_xor_sync(0xFFFFFFFF, p0, 1);
        p0 += __shfl_xor_sync(0xFFFFFFFF, p0, 2);
        p1 += __shfl_xor_sync(0xFFFFFFFF, p1, 1);
        p1 += __shfl_xor_sync(0xFFFFFFFF, p1, 2);
        if ((lane & 3) == 0) {
            atomicAdd(&sacc[r],     p0);
            atomicAdd(&sacc[r + 8], p1);
        }
    }
    __syncthreads();
    if (tid < 128)
        g_part[(size_t)blockIdx.x * (BATCH * SEQ) + (size_t)b * SEQ + s0 + tid] = sacc[tid];
}

// deterministic fixed-order reduction of the 8 n-tile partials
__global__ __launch_bounds__(256)
void score_reduce_kernel(const float* __restrict__ bV)
{
    int i = blockIdx.x * 256 + threadIdx.x;
    float s = 0.f;
    #pragma unroll
    for (int t = 0; t < NTILES; t++)
        s += g_part[(size_t)t * (BATCH * SEQ) + i];
    g_scores[i] = s + bV[0];
}

// ======================= fp32 SGEMM (small GEMMs) =======================
__global__ __launch_bounds__(256)
void sgemm_bias_kernel(const float* __restrict__ A, int lda,
                       const float* __restrict__ B, int ldb,
                       float* __restrict__ C, int ldc,
                       const float* __restrict__ bias,
                       int K)
{
    __shared__ float As[16][128 + 4];
    __shared__ float Bs[16][64];

    const int tid = threadIdx.x;
    const int n0  = blockIdx.x * 64;
    const int tm  = (tid >> 4) * 8;
    const int tn  = (tid & 15) * 4;

    float acc[8][4];
    #pragma unroll
    for (int i = 0; i < 8; i++)
        #pragma unroll
        for (int j = 0; j < 4; j++) acc[i][j] = 0.f;

    for (int kk = 0; kk < K; kk += 16) {
        #pragma unroll
        for (int it = 0; it < 2; it++) {
            int t4 = it * 256 + tid;
            int row = t4 >> 2, col = (t4 & 3) * 4;
            float4 v = *reinterpret_cast<const float4*>(&A[(size_t)row * lda + kk + col]);
            As[col + 0][row] = v.x; As[col + 1][row] = v.y;
            As[col + 2][row] = v.z; As[col + 3][row] = v.w;
        }
        {
            int row = tid >> 4, c4 = (tid & 15) * 4;
            *reinterpret_cast<float4*>(&Bs[row][c4]) =
                *reinterpret_cast<const float4*>(&B[(size_t)(kk + row) * ldb + n0 + c4]);
        }
        __syncthreads();
        #pragma unroll
        for (int k = 0; k < 16; k++) {
            float ra[8], rb[4];
            *reinterpret_cast<float4*>(&ra[0]) = *reinterpret_cast<const float4*>(&As[k][tm]);
            *reinterpret_cast<float4*>(&ra[4]) = *reinterpret_cast<const float4*>(&As[k][tm + 4]);
            *reinterpret_cast<float4*>(&rb[0]) = *reinterpret_cast<const float4*>(&Bs[k][tn]);
            #pragma unroll
            for (int i = 0; i < 8; i++)
                #pragma unroll
                for (int j = 0; j < 4; j++)
                    acc[i][j] += ra[i] * rb[j];
        }
        __syncthreads();
    }
    #pragma unroll
    for (int j = 0; j < 4; j++) {
        float bv = bias ? bias[n0 + tn + j] : 0.f;
        #pragma unroll
        for (int i = 0; i < 8; i++)
            C[(size_t)(tm + i) * ldc + n0 + tn + j] = acc[i][j] + bv;
    }
}

// ======================= remaining pipeline =======================
__global__ __launch_bounds__(256)
void softmax_kernel(float* __restrict__ out_attn)
{
    __shared__ float sh[SEQ];
    __shared__ float red[256];
    const int b = blockIdx.x, tid = threadIdx.x;

    float m = -1e30f;
    for (int i = tid; i < SEQ; i += 256) {
        float v = g_scores[(size_t)b * SEQ + i];
        sh[i] = v;
        m = fmaxf(m, v);
    }
    red[tid] = m; __syncthreads();
    for (int s = 128; s > 0; s >>= 1) {
        if (tid < s) red[tid] = fmaxf(red[tid], red[tid + s]);
        __syncthreads();
    }
    m = red[0]; __syncthreads();

    float sum = 0.f;
    for (int i = tid; i < SEQ; i += 256) {
        float e = expf(sh[i] - m);
        sh[i] = e;
        sum += e;
    }
    red[tid] = sum; __syncthreads();
    for (int s = 128; s > 0; s >>= 1) {
        if (tid < s) red[tid] += red[tid + s];
        __syncthreads();
    }
    float inv = 1.f / red[0];
    for (int i = tid; i < SEQ; i += 256)
        out_attn[(size_t)b * SEQ + i] = sh[i] * inv;
}

__global__ __launch_bounds__(256)
void context_kernel(const float* __restrict__ enc, const float* __restrict__ attn)
{
    __shared__ float w[SEQ];
    const int b = blockIdx.y, u0 = blockIdx.x * 256, tid = threadIdx.x;

    for (int i = tid; i < SEQ; i += 256)
        w[i] = attn[(size_t)b * SEQ + i];
    __syncthreads();

    const float* e = enc + (size_t)b * SEQ * UNITS + u0 + tid;
    float acc = 0.f;
    #pragma unroll 8
    for (int s = 0; s < SEQ; s++)
        acc += w[s] * e[(size_t)s * UNITS];
    g_gin[(size_t)b * GINLEN + u0 + tid] = acc;
}

__global__ void copyx_kernel(const float* __restrict__ x)
{
    int i = blockIdx.x * 256 + threadIdx.x;
    if (i < BATCH * INDIM) {
        int b = i >> 6, u = i & 63;
        g_gin[(size_t)b * GINLEN + UNITS + u] = x[i];
    }
}

__global__ __launch_bounds__(256)
void gates_kernel(const float* __restrict__ hidden)
{
    int i = blockIdx.x * 256 + threadIdx.x;
    int b = i >> 10, u = i & 1023;
    size_t base = (size_t)b * G3U;
    float z = 1.f / (1.f + expf(-(g_xg[base + u] + g_hwr[base + u])));
    float r = 1.f / (1.f + expf(-(g_xg[base + UNITS + u] + g_hwr[base + UNITS + u])));
    g_z[i]  = z;
    g_rh[i] = r * hidden[i];
}

__global__ __launch_bounds__(256)
void state_kernel(const float* __restrict__ hidden, float* __restrict__ out_state)
{
    int i = blockIdx.x * 256 + threadIdx.x;
    int b = i >> 10, u = i & 1023;
    float hh = tanhf(g_xg[(size_t)b * G3U + 2 * UNITS + u] + g_rhwr[i]);
    float z  = g_z[i];
    float st = z * hidden[i] + (1.f - z) * hh;
    out_state[i] = st;
    g_state[i]   = st;
}

// ----------------------------------------------------------------------------
extern "C" void kernel_launch(void* const* d_in, const int* in_sizes, int n_in,
                              void* d_out_v, int out_size)
{
    const float* x      = (const float*)d_in[0];
    const float* hidden = (const float*)d_in[1];
    const float* enc    = (const float*)d_in[2];
    const float* W1     = (const float*)d_in[3];
    const float* b1     = (const float*)d_in[4];
    const float* W2     = (const float*)d_in[5];
    const float* b2     = (const float*)d_in[6];
    const float* V      = (const float*)d_in[7];
    const float* bV     = (const float*)d_in[8];
    const float* Wk     = (const float*)d_in[9];
    const float* Wr     = (const float*)d_in[10];
    const float* bg     = (const float*)d_in[11];
    const float* Wfc    = (const float*)d_in[12];
    const float* bfc    = (const float*)d_in[13];

    float* d_out     = (float*)d_out_v;
    float* out_fc    = d_out;
    float* out_state = d_out + BATCH * INDIM;
    float* out_attn  = d_out + BATCH * INDIM + BATCH * UNITS;

    float *q, *gin, *rh, *state, *xg, *hwr, *rhwr;
    cudaGetSymbolAddress((void**)&q,     g_q);
    cudaGetSymbolAddress((void**)&gin,   g_gin);
    cudaGetSymbolAddress((void**)&rh,    g_rh);
    cudaGetSymbolAddress((void**)&state, g_state);
    cudaGetSymbolAddress((void**)&xg,    g_xg);
    cudaGetSymbolAddress((void**)&hwr,   g_hwr);
    cudaGetSymbolAddress((void**)&rhwr,  g_rhwr);

    cudaFuncSetAttribute(score_mma_kernel,
                         cudaFuncAttributeMaxDynamicSharedMemorySize, SCORE_SMEM);

    // 1. precompute bf16 hi/lo operands
    split_enc_kernel<<<(int)(((size_t)BATCH * SEQ * UNITS) / (256 * 8)), 256>>>(enc);
    w1_split_kernel<<<dim3(32, 32), dim3(32, 8)>>>(W1);
    // 2. q = hidden @ W2 + b2
    sgemm_bias_kernel<<<dim3(UNITS / 64), 256>>>(hidden, UNITS, W2, UNITS, q, UNITS, b2, UNITS);
    // 3. tensor-core score GEMM + fused tanh/V epilogue (partials per n-tile)
    score_mma_kernel<<<dim3(NTILES, SEQ / 128, BATCH), 256, SCORE_SMEM>>>(q, b1, V);
    score_reduce_kernel<<<(BATCH * SEQ) / 256, 256>>>(bV);
    // 4. softmax -> attention weights (output slab 3)
    softmax_kernel<<<BATCH, 256>>>(out_attn);
    // 5. gin = [context | x]
    copyx_kernel<<<(BATCH * INDIM + 255) / 256, 256>>>(x);
    context_kernel<<<dim3(UNITS / 256, BATCH), 256>>>(enc, out_attn);
    // 6. GRU projections
    sgemm_bias_kernel<<<dim3(G3U / 64), 256>>>(gin, GINLEN, Wk, G3U, xg, G3U, bg, GINLEN);
    sgemm_bias_kernel<<<dim3(G3U / 64), 256>>>(hidden, UNITS, Wr, G3U, hwr, G3U, nullptr, UNITS);
    // 7. gates
    gates_kernel<<<(BATCH * UNITS) / 256, 256>>>(hidden);
    // 8. (r*h) @ Wr_h
    sgemm_bias_kernel<<<dim3(UNITS / 64), 256>>>(rh, UNITS, Wr + 2 * UNITS, G3U, rhwr, UNITS, nullptr, UNITS);
    // 9. state (output slab 2)
    state_kernel<<<(BATCH * UNITS) / 256, 256>>>(hidden, out_state);
    // 10. out = state @ Wfc + bfc (output slab 1)
    sgemm_bias_kernel<<<dim3(INDIM / 64), 256>>>(state, UNITS, Wfc, INDIM, out_fc, INDIM, bfc, UNITS);
}

// round 4
// speedup vs baseline: 2.5133x; 1.1726x over previous
#include <cuda_runtime.h>
#include <cuda_bf16.h>
#include <cstdint>
#include <cstddef>

// ----------------------------------------------------------------------------
// Decoder step: Bahdanau attention + GRU cell + fc, B=128, S=1024, U=1024.
// Score GEMM on mma.sync bf16 with hi/lo split (3-term, ~3e-6 rel err).
// R4: 2 CTAs/SM (96KB smem, <=128 regs), 3-stage cp.async, XOR-swizzled 64B rows.
// ----------------------------------------------------------------------------

#define BATCH   128
#define SEQ     1024
#define UNITS   1024
#define INDIM   64
#define GINLEN  (UNITS + INDIM)   // 1088
#define G3U     (3 * UNITS)       // 3072
#define NTILES  8                 // 1024 / 128 n-tiles

// ---------------- scratch (no allocations allowed) ----------------
__device__ __align__(16) __nv_bfloat16 g_enc_hi[(size_t)BATCH * SEQ * UNITS];
__device__ __align__(16) __nv_bfloat16 g_enc_lo[(size_t)BATCH * SEQ * UNITS];
__device__ __align__(16) __nv_bfloat16 g_w1t_hi[(size_t)UNITS * UNITS];   // W1^T
__device__ __align__(16) __nv_bfloat16 g_w1t_lo[(size_t)UNITS * UNITS];
__device__ __align__(16) float g_q     [BATCH * UNITS];
__device__ __align__(16) float g_part  [NTILES * BATCH * SEQ];
__device__ __align__(16) float g_scores[BATCH * SEQ];
__device__ __align__(16) float g_gin   [BATCH * GINLEN];
__device__ __align__(16) float g_xg    [BATCH * G3U];
__device__ __align__(16) float g_hwr   [BATCH * G3U];
__device__ __align__(16) float g_z     [BATCH * UNITS];
__device__ __align__(16) float g_rh    [BATCH * UNITS];
__device__ __align__(16) float g_rhwr  [BATCH * UNITS];
__device__ __align__(16) float g_state [BATCH * UNITS];

// ======================= PTX helpers =======================
__device__ __forceinline__ uint32_t smem_u32(const void* p) {
    uint32_t a;
    asm("{ .reg .u64 t; cvta.to.shared.u64 t, %1; cvt.u32.u64 %0, t; }" : "=r"(a) : "l"(p));
    return a;
}
#define CP_ASYNC16(dst, src) \
    asm volatile("cp.async.cg.shared.global [%0], [%1], 16;" :: "r"(dst), "l"(src))
#define CP_COMMIT() asm volatile("cp.async.commit_group;" ::: "memory")

__device__ __forceinline__ void ldsm_x4(uint32_t r[4], uint32_t addr) {
    asm volatile("ldmatrix.sync.aligned.m8n8.x4.shared.b16 {%0,%1,%2,%3}, [%4];"
                 : "=r"(r[0]), "=r"(r[1]), "=r"(r[2]), "=r"(r[3]) : "r"(addr));
}
__device__ __forceinline__ void ldsm_x2(uint32_t r[2], uint32_t addr) {
    asm volatile("ldmatrix.sync.aligned.m8n8.x2.shared.b16 {%0,%1}, [%2];"
                 : "=r"(r[0]), "=r"(r[1]) : "r"(addr));
}
__device__ __forceinline__ void mma_bf16(float c[4], const uint32_t a[4], const uint32_t b[2]) {
    asm volatile(
        "mma.sync.aligned.m16n8k16.row.col.f32.bf16.bf16.f32 "
        "{%0,%1,%2,%3}, {%4,%5,%6,%7}, {%8,%9}, {%0,%1,%2,%3};"
        : "+f"(c[0]), "+f"(c[1]), "+f"(c[2]), "+f"(c[3])
        : "r"(a[0]), "r"(a[1]), "r"(a[2]), "r"(a[3]), "r"(b[0]), "r"(b[1]));
}

// ======================= precompute kernels =======================
__global__ __launch_bounds__(256)
void split_enc_kernel(const float* __restrict__ enc)
{
    size_t i = ((size_t)blockIdx.x * 256 + threadIdx.x) * 8;
    float4 v0 = *reinterpret_cast<const float4*>(enc + i);
    float4 v1 = *reinterpret_cast<const float4*>(enc + i + 4);
    float x[8] = {v0.x, v0.y, v0.z, v0.w, v1.x, v1.y, v1.z, v1.w};
    union { __nv_bfloat16 h[8]; uint4 u; } hi, lo;
    #pragma unroll
    for (int j = 0; j < 8; j++) {
        __nv_bfloat16 h = __float2bfloat16(x[j]);
        hi.h[j] = h;
        lo.h[j] = __float2bfloat16(x[j] - __bfloat162float(h));
    }
    *reinterpret_cast<uint4*>(g_enc_hi + i) = hi.u;
    *reinterpret_cast<uint4*>(g_enc_lo + i) = lo.u;
}

// W1 [k][n] fp32 -> W1^T [n][k] hi/lo bf16
__global__ __launch_bounds__(256)
void w1_split_kernel(const float* __restrict__ W1)
{
    __shared__ float tile[32][33];
    int n0 = blockIdx.x * 32, k0 = blockIdx.y * 32;
    int tx = threadIdx.x, ty = threadIdx.y;   // 32 x 8
    #pragma unroll
    for (int i = 0; i < 4; i++)
        tile[ty + i * 8][tx] = W1[(size_t)(k0 + ty + i * 8) * UNITS + n0 + tx];
    __syncthreads();
    #pragma unroll
    for (int i = 0; i < 4; i++) {
        float v = tile[tx][ty + i * 8];
        __nv_bfloat16 h = __float2bfloat16(v);
        size_t o = (size_t)(n0 + ty + i * 8) * UNITS + k0 + tx;
        g_w1t_hi[o] = h;
        g_w1t_lo[o] = __float2bfloat16(v - __bfloat162float(h));
    }
}

// ======================= warp-MMA score GEMM =======================
// CTA: (b, s-tile 128, n-tile 128). K = 1024 in 32 chunks of 32 bf16 (64B rows).
// Tiles per stage: A_hi | A_lo | B_hi | B_lo, each 128 rows x 64B = 8KB,
// XOR swizzle: 16B-chunk c -> c ^ ((row>>1)&3)  (conflict-free ldmatrix).
// 3 stages -> 96KB smem; __launch_bounds__(256,2) -> 2 CTAs/SM, 16 warps.
#define T_AH    0
#define T_AL    8192
#define T_BH    16384
#define T_BL    24576
#define STAGE_B 32768
#define NCHUNK  32
#define SCORE_SMEM (3 * STAGE_B)          // 98304

__device__ __forceinline__ void fill_stage(uint32_t stage,
                                           const char* eh, const char* el,
                                           const char* bh, const char* bl,
                                           int chunk, int tid)
{
    const int kb = chunk * 64;            // 32 bf16 = 64 bytes
    #pragma unroll
    for (int t = 0; t < 2; t++) {         // 512 (row,c) pairs per tile / 256 thr
        int idx = t * 256 + tid;
        int row = idx >> 2, c = idx & 3;
        uint32_t so = (uint32_t)(row * 64 + ((c ^ ((row >> 1) & 3)) << 4));
        size_t   go = (size_t)row * (UNITS * 2) + kb + c * 16;
        CP_ASYNC16(stage + T_AH + so, eh + go);
        CP_ASYNC16(stage + T_AL + so, el + go);
        CP_ASYNC16(stage + T_BH + so, bh + go);
        CP_ASYNC16(stage + T_BL + so, bl + go);
    }
}

__global__ __launch_bounds__(256, 2)
void score_mma_kernel(const float* __restrict__ q,
                      const float* __restrict__ b1,
                      const float* __restrict__ V)
{
    extern __shared__ __align__(128) char smem[];
    __shared__ float sacc[128];
    const uint32_t sb = smem_u32(smem);

    const int tid    = threadIdx.x;
    const int lane   = tid & 31;
    const int wid    = tid >> 5;
    const int warp_m = wid >> 2;          // 0..1  (64 rows each)
    const int warp_n = wid & 3;           // 0..3  (32 cols each)
    const int n0     = blockIdx.x * 128;
    const int s0     = blockIdx.y * 128;
    const int b      = blockIdx.z;

    if (tid < 128) sacc[tid] = 0.f;

    const char* eh = (const char*)(g_enc_hi + ((size_t)b * SEQ + s0) * UNITS);
    const char* el = (const char*)(g_enc_lo + ((size_t)b * SEQ + s0) * UNITS);
    const char* bh = (const char*)(g_w1t_hi + (size_t)n0 * UNITS);
    const char* bl = (const char*)(g_w1t_lo + (size_t)n0 * UNITS);

    fill_stage(sb,               eh, el, bh, bl, 0, tid); CP_COMMIT();
    fill_stage(sb + STAGE_B,     eh, el, bh, bl, 1, tid); CP_COMMIT();
    fill_stage(sb + 2 * STAGE_B, eh, el, bh, bl, 2, tid); CP_COMMIT();

    float acc[4][4][4];
    #pragma unroll
    for (int mi = 0; mi < 4; mi++)
        #pragma unroll
        for (int ni = 0; ni < 4; ni++)
            #pragma unroll
            for (int c = 0; c < 4; c++) acc[mi][ni][c] = 0.f;

    // Per-thread ldmatrix row offsets + swizzle XOR (fixed across chunks)
    uint32_t a_off[4], b_off[4];
    uint32_t xa[4], xb[4];
    #pragma unroll
    for (int mi = 0; mi < 4; mi++) {
        int row = warp_m * 64 + mi * 16 + (lane & 15);
        a_off[mi] = (uint32_t)row * 64;
        xa[mi]    = (uint32_t)((row >> 1) & 3);
    }
    #pragma unroll
    for (int ni = 0; ni < 4; ni++) {
        int row = warp_n * 32 + ni * 8 + (lane & 7);
        b_off[ni] = (uint32_t)row * 64;
        xb[ni]    = (uint32_t)((row >> 1) & 3);
    }
    const uint32_t caA = (uint32_t)(lane >> 4);        // A k-half
    const uint32_t caB = (uint32_t)((lane >> 3) & 1);  // B k-half

    #pragma unroll 1
    for (int c = 0; c < NCHUNK; c++) {
        if (c < NCHUNK - 2)      asm volatile("cp.async.wait_group 2;" ::: "memory");
        else if (c == NCHUNK - 2) asm volatile("cp.async.wait_group 1;" ::: "memory");
        else                     asm volatile("cp.async.wait_group 0;" ::: "memory");
        __syncthreads();

        const uint32_t slot = sb + (uint32_t)(c % 3) * STAGE_B;

        #pragma unroll
        for (int j = 0; j < 2; j++) {     // two k16 steps per 32-chunk
            uint32_t bhf[4][2], blf[4][2];
            #pragma unroll
            for (int ni = 0; ni < 4; ni++) {
                uint32_t cB = (uint32_t)(j * 2) + caB;
                uint32_t ad = slot + T_BH + b_off[ni] + ((cB ^ xb[ni]) << 4);
                ldsm_x2(bhf[ni], ad);
                ldsm_x2(blf[ni], ad + (T_BL - T_BH));
            }
            #pragma unroll
            for (int mi = 0; mi < 4; mi++) {
                uint32_t cA = (uint32_t)(j * 2) + caA;
                uint32_t ad = slot + T_AH + a_off[mi] + ((cA ^ xa[mi]) << 4);
                uint32_t ah[4], al[4];
                ldsm_x4(ah, ad);
                ldsm_x4(al, ad + (T_AL - T_AH));
                #pragma unroll
                for (int ni = 0; ni < 4; ni++) {
                    mma_bf16(acc[mi][ni], ah, bhf[ni]);
                    mma_bf16(acc[mi][ni], al, bhf[ni]);
                    mma_bf16(acc[mi][ni], ah, blf[ni]);
                }
            }
        }
        __syncthreads();
        if (c + 3 < NCHUNK) {
            fill_stage(slot, eh, el, bh, bl, c + 3, tid);
            CP_COMMIT();
        }
    }

    // Epilogue: part[s] = sum_n V[n]*tanh(acc + q[b,n] + b1[n])
    const size_t qb = (size_t)b * UNITS;
    #pragma unroll
    for (int mi = 0; mi < 4; mi++) {
        float p0 = 0.f, p1 = 0.f;
        const int r = warp_m * 64 + mi * 16 + (lane >> 2);
        #pragma unroll
        for (int ni = 0; ni < 4; ni++) {
            #pragma unroll
            for (int cc = 0; cc < 4; cc++) {
                int n = n0 + warp_n * 32 + ni * 8 + (lane & 3) * 2 + (cc & 1);
                float t = V[n] * tanhf(acc[mi][ni][cc] + q[qb + n] + b1[n]);
                if (cc < 2) p0 += t; else p1 += t;
            }
        }
        p0 += __shfl_xor_sync(0xFFFFFFFF, p0, 1);
        p0 += __shfl_xor_sync(0xFFFFFFFF, p0, 2);
        p1 += __shfl_xor_sync(0xFFFFFFFF, p1, 1);
        p1 += __shfl_xor_sync(0xFFFFFFFF, p1, 2);
        if ((lane & 3) == 0) {
            atomicAdd(&sacc[r],     p0);
            atomicAdd(&sacc[r + 8], p1);
        }
    }
    __syncthreads();
    if (tid < 128)
        g_part[(size_t)blockIdx.x * (BATCH * SEQ) + (size_t)b * SEQ + s0 + tid] = sacc[tid];
}

// deterministic fixed-order reduction of the 8 n-tile partials
__global__ __launch_bounds__(256)
void score_reduce_kernel(const float* __restrict__ bV)
{
    int i = blockIdx.x * 256 + threadIdx.x;
    float s = 0.f;
    #pragma unroll
    for (int t = 0; t < NTILES; t++)
        s += g_part[(size_t)t * (BATCH * SEQ) + i];
    g_scores[i] = s + bV[0];
}

// ======================= fp32 SGEMM (small GEMMs) =======================
__global__ __launch_bounds__(256)
void sgemm_bias_kernel(const float* __restrict__ A, int lda,
                       const float* __restrict__ B, int ldb,
                       float* __restrict__ C, int ldc,
                       const float* __restrict__ bias,
                       int K)
{
    __shared__ float As[16][128 + 4];
    __shared__ float Bs[16][64];

    const int tid = threadIdx.x;
    const int n0  = blockIdx.x * 64;
    const int tm  = (tid >> 4) * 8;
    const int tn  = (tid & 15) * 4;

    float acc[8][4];
    #pragma unroll
    for (int i = 0; i < 8; i++)
        #pragma unroll
        for (int j = 0; j < 4; j++) acc[i][j] = 0.f;

    for (int kk = 0; kk < K; kk += 16) {
        #pragma unroll
        for (int it = 0; it < 2; it++) {
            int t4 = it * 256 + tid;
            int row = t4 >> 2, col = (t4 & 3) * 4;
            float4 v = *reinterpret_cast<const float4*>(&A[(size_t)row * lda + kk + col]);
            As[col + 0][row] = v.x; As[col + 1][row] = v.y;
            As[col + 2][row] = v.z; As[col + 3][row] = v.w;
        }
        {
            int row = tid >> 4, c4 = (tid & 15) * 4;
            *reinterpret_cast<float4*>(&Bs[row][c4]) =
                *reinterpret_cast<const float4*>(&B[(size_t)(kk + row) * ldb + n0 + c4]);
        }
        __syncthreads();
        #pragma unroll
        for (int k = 0; k < 16; k++) {
            float ra[8], rb[4];
            *reinterpret_cast<float4*>(&ra[0]) = *reinterpret_cast<const float4*>(&As[k][tm]);
            *reinterpret_cast<float4*>(&ra[4]) = *reinterpret_cast<const float4*>(&As[k][tm + 4]);
            *reinterpret_cast<float4*>(&rb[0]) = *reinterpret_cast<const float4*>(&Bs[k][tn]);
            #pragma unroll
            for (int i = 0; i < 8; i++)
                #pragma unroll
                for (int j = 0; j < 4; j++)
                    acc[i][j] += ra[i] * rb[j];
        }
        __syncthreads();
    }
    #pragma unroll
    for (int j = 0; j < 4; j++) {
        float bv = bias ? bias[n0 + tn + j] : 0.f;
        #pragma unroll
        for (int i = 0; i < 8; i++)
            C[(size_t)(tm + i) * ldc + n0 + tn + j] = acc[i][j] + bv;
    }
}

// ======================= remaining pipeline =======================
__global__ __launch_bounds__(256)
void softmax_kernel(float* __restrict__ out_attn)
{
    __shared__ float sh[SEQ];
    __shared__ float red[256];
    const int b = blockIdx.x, tid = threadIdx.x;

    float m = -1e30f;
    for (int i = tid; i < SEQ; i += 256) {
        float v = g_scores[(size_t)b * SEQ + i];
        sh[i] = v;
        m = fmaxf(m, v);
    }
    red[tid] = m; __syncthreads();
    for (int s = 128; s > 0; s >>= 1) {
        if (tid < s) red[tid] = fmaxf(red[tid], red[tid + s]);
        __syncthreads();
    }
    m = red[0]; __syncthreads();

    float sum = 0.f;
    for (int i = tid; i < SEQ; i += 256) {
        float e = expf(sh[i] - m);
        sh[i] = e;
        sum += e;
    }
    red[tid] = sum; __syncthreads();
    for (int s = 128; s > 0; s >>= 1) {
        if (tid < s) red[tid] += red[tid + s];
        __syncthreads();
    }
    float inv = 1.f / red[0];
    for (int i = tid; i < SEQ; i += 256)
        out_attn[(size_t)b * SEQ + i] = sh[i] * inv;
}

__global__ __launch_bounds__(256)
void context_kernel(const float* __restrict__ enc, const float* __restrict__ attn)
{
    __shared__ float w[SEQ];
    const int b = blockIdx.y, u0 = blockIdx.x * 256, tid = threadIdx.x;

    for (int i = tid; i < SEQ; i += 256)
        w[i] = attn[(size_t)b * SEQ + i];
    __syncthreads();

    const float* e = enc + (size_t)b * SEQ * UNITS + u0 + tid;
    float acc = 0.f;
    #pragma unroll 8
    for (int s = 0; s < SEQ; s++)
        acc += w[s] * e[(size_t)s * UNITS];
    g_gin[(size_t)b * GINLEN + u0 + tid] = acc;
}

__global__ void copyx_kernel(const float* __restrict__ x)
{
    int i = blockIdx.x * 256 + threadIdx.x;
    if (i < BATCH * INDIM) {
        int b = i >> 6, u = i & 63;
        g_gin[(size_t)b * GINLEN + UNITS + u] = x[i];
    }
}

__global__ __launch_bounds__(256)
void gates_kernel(const float* __restrict__ hidden)
{
    int i = blockIdx.x * 256 + threadIdx.x;
    int b = i >> 10, u = i & 1023;
    size_t base = (size_t)b * G3U;
    float z = 1.f / (1.f + expf(-(g_xg[base + u] + g_hwr[base + u])));
    float r = 1.f / (1.f + expf(-(g_xg[base + UNITS + u] + g_hwr[base + UNITS + u])));
    g_z[i]  = z;
    g_rh[i] = r * hidden[i];
}

__global__ __launch_bounds__(256)
void state_kernel(const float* __restrict__ hidden, float* __restrict__ out_state)
{
    int i = blockIdx.x * 256 + threadIdx.x;
    int b = i >> 10, u = i & 1023;
    float hh = tanhf(g_xg[(size_t)b * G3U + 2 * UNITS + u] + g_rhwr[i]);
    float z  = g_z[i];
    float st = z * hidden[i] + (1.f - z) * hh;
    out_state[i] = st;
    g_state[i]   = st;
}

// ----------------------------------------------------------------------------
extern "C" void kernel_launch(void* const* d_in, const int* in_sizes, int n_in,
                              void* d_out_v, int out_size)
{
    const float* x      = (const float*)d_in[0];
    const float* hidden = (const float*)d_in[1];
    const float* enc    = (const float*)d_in[2];
    const float* W1     = (const float*)d_in[3];
    const float* b1     = (const float*)d_in[4];
    const float* W2     = (const float*)d_in[5];
    const float* b2     = (const float*)d_in[6];
    const float* V      = (const float*)d_in[7];
    const float* bV     = (const float*)d_in[8];
    const float* Wk     = (const float*)d_in[9];
    const float* Wr     = (const float*)d_in[10];
    const float* bg     = (const float*)d_in[11];
    const float* Wfc    = (const float*)d_in[12];
    const float* bfc    = (const float*)d_in[13];

    float* d_out     = (float*)d_out_v;
    float* out_fc    = d_out;
    float* out_state = d_out + BATCH * INDIM;
    float* out_attn  = d_out + BATCH * INDIM + BATCH * UNITS;

    float *q, *gin, *rh, *state, *xg, *hwr, *rhwr;
    cudaGetSymbolAddress((void**)&q,     g_q);
    cudaGetSymbolAddress((void**)&gin,   g_gin);
    cudaGetSymbolAddress((void**)&rh,    g_rh);
    cudaGetSymbolAddress((void**)&state, g_state);
    cudaGetSymbolAddress((void**)&xg,    g_xg);
    cudaGetSymbolAddress((void**)&hwr,   g_hwr);
    cudaGetSymbolAddress((void**)&rhwr,  g_rhwr);

    cudaFuncSetAttribute(score_mma_kernel,
                         cudaFuncAttributeMaxDynamicSharedMemorySize, SCORE_SMEM);

    // 1. precompute bf16 hi/lo operands
    split_enc_kernel<<<(int)(((size_t)BATCH * SEQ * UNITS) / (256 * 8)), 256>>>(enc);
    w1_split_kernel<<<dim3(32, 32), dim3(32, 8)>>>(W1);
    // 2. q = hidden @ W2 + b2
    sgemm_bias_kernel<<<dim3(UNITS / 64), 256>>>(hidden, UNITS, W2, UNITS, q, UNITS, b2, UNITS);
    // 3. tensor-core score GEMM + fused tanh/V epilogue (partials per n-tile)
    score_mma_kernel<<<dim3(NTILES, SEQ / 128, BATCH), 256, SCORE_SMEM>>>(q, b1, V);
    score_reduce_kernel<<<(BATCH * SEQ) / 256, 256>>>(bV);
    // 4. softmax -> attention weights (output slab 3)
    softmax_kernel<<<BATCH, 256>>>(out_attn);
    // 5. gin = [context | x]
    copyx_kernel<<<(BATCH * INDIM + 255) / 256, 256>>>(x);
    context_kernel<<<dim3(UNITS / 256, BATCH), 256>>>(enc, out_attn);
    // 6. GRU projections
    sgemm_bias_kernel<<<dim3(G3U / 64), 256>>>(gin, GINLEN, Wk, G3U, xg, G3U, bg, GINLEN);
    sgemm_bias_kernel<<<dim3(G3U / 64), 256>>>(hidden, UNITS, Wr, G3U, hwr, G3U, nullptr, UNITS);
    // 7. gates
    gates_kernel<<<(BATCH * UNITS) / 256, 256>>>(hidden);
    // 8. (r*h) @ Wr_h
    sgemm_bias_kernel<<<dim3(UNITS / 64), 256>>>(rh, UNITS, Wr + 2 * UNITS, G3U, rhwr, UNITS, nullptr, UNITS);
    // 9. state (output slab 2)
    state_kernel<<<(BATCH * UNITS) / 256, 256>>>(hidden, out_state);
    // 10. out = state @ Wfc + bfc (output slab 1)
    sgemm_bias_kernel<<<dim3(INDIM / 64), 256>>>(state, UNITS, Wfc, INDIM, out_fc, INDIM, bfc, UNITS);
}

// round 7
// speedup vs baseline: 2.6080x; 1.0377x over previous
#include <cuda_runtime.h>
#include <cuda_bf16.h>
#include <cstdint>
#include <cstddef>

// ----------------------------------------------------------------------------
// Decoder step: Bahdanau attention + GRU cell + fc, B=128, S=1024, U=1024.
// Score GEMM on mma.sync bf16 hi/lo split (3-term, ~3e-6 rel err).
// R6 = R5 resubmit (infra failure): single-sync 3-stage pipeline, ldmatrix.x4
// for B, fused reduce+softmax, dual-GEMM launch for the GRU projections.
// ----------------------------------------------------------------------------

#define BATCH   128
#define SEQ     1024
#define UNITS   1024
#define INDIM   64
#define GINLEN  (UNITS + INDIM)   // 1088
#define G3U     (3 * UNITS)       // 3072
#define NTILES  8                 // 1024 / 128 n-tiles

// ---------------- scratch (no allocations allowed) ----------------
__device__ __align__(16) __nv_bfloat16 g_enc_hi[(size_t)BATCH * SEQ * UNITS];
__device__ __align__(16) __nv_bfloat16 g_enc_lo[(size_t)BATCH * SEQ * UNITS];
__device__ __align__(16) __nv_bfloat16 g_w1t_hi[(size_t)UNITS * UNITS];   // W1^T
__device__ __align__(16) __nv_bfloat16 g_w1t_lo[(size_t)UNITS * UNITS];
__device__ __align__(16) float g_q     [BATCH * UNITS];
__device__ __align__(16) float g_part  [NTILES * BATCH * SEQ];
__device__ __align__(16) float g_gin   [BATCH * GINLEN];
__device__ __align__(16) float g_xg    [BATCH * G3U];
__device__ __align__(16) float g_hwr   [BATCH * G3U];
__device__ __align__(16) float g_z     [BATCH * UNITS];
__device__ __align__(16) float g_rh    [BATCH * UNITS];
__device__ __align__(16) float g_rhwr  [BATCH * UNITS];
__device__ __align__(16) float g_state [BATCH * UNITS];

// ======================= PTX helpers =======================
__device__ __forceinline__ uint32_t smem_u32(const void* p) {
    uint32_t a;
    asm("{ .reg .u64 t; cvta.to.shared.u64 t, %1; cvt.u32.u64 %0, t; }" : "=r"(a) : "l"(p));
    return a;
}
#define CP_ASYNC16(dst, src) \
    asm volatile("cp.async.cg.shared.global [%0], [%1], 16;" :: "r"(dst), "l"(src))
#define CP_COMMIT() asm volatile("cp.async.commit_group;" ::: "memory")

__device__ __forceinline__ void ldsm_x4(uint32_t r[4], uint32_t addr) {
    asm volatile("ldmatrix.sync.aligned.m8n8.x4.shared.b16 {%0,%1,%2,%3}, [%4];"
                 : "=r"(r[0]), "=r"(r[1]), "=r"(r[2]), "=r"(r[3]) : "r"(addr));
}
__device__ __forceinline__ void mma_bf16(float c[4], const uint32_t a[4], const uint32_t b[2]) {
    asm volatile(
        "mma.sync.aligned.m16n8k16.row.col.f32.bf16.bf16.f32 "
        "{%0,%1,%2,%3}, {%4,%5,%6,%7}, {%8,%9}, {%0,%1,%2,%3};"
        : "+f"(c[0]), "+f"(c[1]), "+f"(c[2]), "+f"(c[3])
        : "r"(a[0]), "r"(a[1]), "r"(a[2]), "r"(a[3]), "r"(b[0]), "r"(b[1]));
}

// ======================= precompute kernels =======================
__global__ __launch_bounds__(256)
void split_enc_kernel(const float* __restrict__ enc)
{
    size_t i = ((size_t)blockIdx.x * 256 + threadIdx.x) * 8;
    float4 v0 = *reinterpret_cast<const float4*>(enc + i);
    float4 v1 = *reinterpret_cast<const float4*>(enc + i + 4);
    float x[8] = {v0.x, v0.y, v0.z, v0.w, v1.x, v1.y, v1.z, v1.w};
    union { __nv_bfloat16 h[8]; uint4 u; } hi, lo;
    #pragma unroll
    for (int j = 0; j < 8; j++) {
        __nv_bfloat16 h = __float2bfloat16(x[j]);
        hi.h[j] = h;
        lo.h[j] = __float2bfloat16(x[j] - __bfloat162float(h));
    }
    *reinterpret_cast<uint4*>(g_enc_hi + i) = hi.u;
    *reinterpret_cast<uint4*>(g_enc_lo + i) = lo.u;
}

// W1 [k][n] fp32 -> W1^T [n][k] hi/lo bf16
__global__ __launch_bounds__(256)
void w1_split_kernel(const float* __restrict__ W1)
{
    __shared__ float tile[32][33];
    int n0 = blockIdx.x * 32, k0 = blockIdx.y * 32;
    int tx = threadIdx.x, ty = threadIdx.y;   // 32 x 8
    #pragma unroll
    for (int i = 0; i < 4; i++)
        tile[ty + i * 8][tx] = W1[(size_t)(k0 + ty + i * 8) * UNITS + n0 + tx];
    __syncthreads();
    #pragma unroll
    for (int i = 0; i < 4; i++) {
        float v = tile[tx][ty + i * 8];
        __nv_bfloat16 h = __float2bfloat16(v);
        size_t o = (size_t)(n0 + ty + i * 8) * UNITS + k0 + tx;
        g_w1t_hi[o] = h;
        g_w1t_lo[o] = __float2bfloat16(v - __bfloat162float(h));
    }
}

// ======================= warp-MMA score GEMM =======================
// CTA: (b, s-tile 128, n-tile 128). K = 1024 in 32 chunks of 32 bf16 (64B rows).
// Stage: A_hi | A_lo | B_hi | B_lo, each 128 x 64B = 8KB, XOR swizzle
// c -> c ^ ((row>>1)&3). 3 stages, single __syncthreads per chunk.
#define T_AH    0
#define T_AL    8192
#define T_BH    16384
#define T_BL    24576
#define STAGE_B 32768
#define NCHUNK  32
#define SCORE_SMEM (3 * STAGE_B)          // 98304

__device__ __forceinline__ void fill_stage(uint32_t stage,
                                           const char* eh, const char* el,
                                           const char* bh, const char* bl,
                                           int chunk, int tid)
{
    const int kb = chunk * 64;            // 32 bf16 = 64 bytes
    #pragma unroll
    for (int t = 0; t < 2; t++) {         // 512 (row,c) pairs per tile / 256 thr
        int idx = t * 256 + tid;
        int row = idx >> 2, c = idx & 3;
        uint32_t so = (uint32_t)(row * 64 + ((c ^ ((row >> 1) & 3)) << 4));
        size_t   go = (size_t)row * (UNITS * 2) + kb + c * 16;
        CP_ASYNC16(stage + T_AH + so, eh + go);
        CP_ASYNC16(stage + T_AL + so, el + go);
        CP_ASYNC16(stage + T_BH + so, bh + go);
        CP_ASYNC16(stage + T_BL + so, bl + go);
    }
}

__global__ __launch_bounds__(256, 2)
void score_mma_kernel(const float* __restrict__ q,
                      const float* __restrict__ b1,
                      const float* __restrict__ V)
{
    extern __shared__ __align__(128) char smem[];
    __shared__ float sacc[128];
    const uint32_t sb = smem_u32(smem);

    const int tid    = threadIdx.x;
    const int lane   = tid & 31;
    const int wid    = tid >> 5;
    const int warp_m = wid >> 2;          // 0..1  (64 rows each)
    const int warp_n = wid & 3;           // 0..3  (32 cols each)
    const int n0     = blockIdx.x * 128;
    const int s0     = blockIdx.y * 128;
    const int b      = blockIdx.z;

    if (tid < 128) sacc[tid] = 0.f;

    const char* eh = (const char*)(g_enc_hi + ((size_t)b * SEQ + s0) * UNITS);
    const char* el = (const char*)(g_enc_lo + ((size_t)b * SEQ + s0) * UNITS);
    const char* bh = (const char*)(g_w1t_hi + (size_t)n0 * UNITS);
    const char* bl = (const char*)(g_w1t_lo + (size_t)n0 * UNITS);

    fill_stage(sb,           eh, el, bh, bl, 0, tid); CP_COMMIT();
    fill_stage(sb + STAGE_B, eh, el, bh, bl, 1, tid); CP_COMMIT();

    float acc[4][4][4];
    #pragma unroll
    for (int mi = 0; mi < 4; mi++)
        #pragma unroll
        for (int ni = 0; ni < 4; ni++)
            #pragma unroll
            for (int c = 0; c < 4; c++) acc[mi][ni][c] = 0.f;

    // A ldmatrix.x4 addressing: lanes 0..15 -> rows, 16..31 -> k-half
    uint32_t a_off[4], xa[4];
    #pragma unroll
    for (int mi = 0; mi < 4; mi++) {
        int row = warp_m * 64 + mi * 16 + (lane & 15);
        a_off[mi] = (uint32_t)row * 64;
        xa[mi]    = (uint32_t)((row >> 1) & 3);
    }
    const uint32_t caA = (uint32_t)(lane >> 4);   // A k-half

    // B ldmatrix.x4 addressing: lane groups of 8 -> (ni within pair, k-half)
    const uint32_t khB    = (uint32_t)((lane >> 3) & 1);
    const uint32_t ni_hB  = (uint32_t)(lane >> 4);
    uint32_t b_off[2], xb[2];
    #pragma unroll
    for (int p = 0; p < 2; p++) {
        int row = warp_n * 32 + p * 16 + (int)ni_hB * 8 + (lane & 7);
        b_off[p] = (uint32_t)row * 64;
        xb[p]    = (uint32_t)((row >> 1) & 3);
    }

    #pragma unroll 1
    for (int c = 0; c < NCHUNK; c++) {
        if (c >= NCHUNK - 1) asm volatile("cp.async.wait_group 0;" ::: "memory");
        else                 asm volatile("cp.async.wait_group 1;" ::: "memory");
        __syncthreads();   // chunk c visible; iteration c-1 MMAs done everywhere

        const uint32_t slot = sb + (uint32_t)(c % 3) * STAGE_B;

        // prefetch chunk c+2 into slot (c+2)%3 (free: consumed at iter c-1)
        if (c + 2 < NCHUNK) {
            fill_stage(sb + (uint32_t)((c + 2) % 3) * STAGE_B, eh, el, bh, bl, c + 2, tid);
            CP_COMMIT();
        }

        #pragma unroll
        for (int j = 0; j < 2; j++) {     // two k16 steps per 32-chunk
            uint32_t bhf[2][4], blf[2][4];
            #pragma unroll
            for (int p = 0; p < 2; p++) {
                uint32_t cB = (uint32_t)(j * 2) + khB;
                uint32_t ad = slot + T_BH + b_off[p] + ((cB ^ xb[p]) << 4);
                ldsm_x4(bhf[p], ad);
                ldsm_x4(blf[p], ad + (T_BL - T_BH));
            }
            #pragma unroll
            for (int mi = 0; mi < 4; mi++) {
                uint32_t cA = (uint32_t)(j * 2) + caA;
                uint32_t ad = slot + T_AH + a_off[mi] + ((cA ^ xa[mi]) << 4);
                uint32_t ah[4], al[4];
                ldsm_x4(ah, ad);
                ldsm_x4(al, ad + (T_AL - T_AH));
                #pragma unroll
                for (int ni = 0; ni < 4; ni++) {
                    const uint32_t* bh2 = &bhf[ni >> 1][(ni & 1) * 2];
                    const uint32_t* bl2 = &blf[ni >> 1][(ni & 1) * 2];
                    mma_bf16(acc[mi][ni], ah, bh2);
                    mma_bf16(acc[mi][ni], al, bh2);
                    mma_bf16(acc[mi][ni], ah, bl2);
                }
            }
        }
    }

    // Epilogue: part[s] = sum_n V[n]*tanh(acc + q[b,n] + b1[n])
    const size_t qb = (size_t)b * UNITS;
    #pragma unroll
    for (int mi = 0; mi < 4; mi++) {
        float p0 = 0.f, p1 = 0.f;
        const int r = warp_m * 64 + mi * 16 + (lane >> 2);
        #pragma unroll
        for (int ni = 0; ni < 4; ni++) {
            #pragma unroll
            for (int cc = 0; cc < 4; cc++) {
                int n = n0 + warp_n * 32 + ni * 8 + (lane & 3) * 2 + (cc & 1);
                float t = V[n] * tanhf(acc[mi][ni][cc] + q[qb + n] + b1[n]);
                if (cc < 2) p0 += t; else p1 += t;
            }
        }
        p0 += __shfl_xor_sync(0xFFFFFFFF, p0, 1);
        p0 += __shfl_xor_sync(0xFFFFFFFF, p0, 2);
        p1 += __shfl_xor_sync(0xFFFFFFFF, p1, 1);
        p1 += __shfl_xor_sync(0xFFFFFFFF, p1, 2);
        if ((lane & 3) == 0) {
            atomicAdd(&sacc[r],     p0);
            atomicAdd(&sacc[r + 8], p1);
        }
    }
    __syncthreads();
    if (tid < 128)
        g_part[(size_t)blockIdx.x * (BATCH * SEQ) + (size_t)b * SEQ + s0 + tid] = sacc[tid];
}

// ======================= fp32 SGEMM (small GEMMs) =======================
__device__ __forceinline__
void sgemm_body(const float* __restrict__ A, int lda,
                const float* __restrict__ B, int ldb,
                float* __restrict__ C, int ldc,
                const float* __restrict__ bias,
                int K, int n0)
{
    __shared__ float As[16][128 + 4];
    __shared__ float Bs[16][64];

    const int tid = threadIdx.x;
    const int tm  = (tid >> 4) * 8;
    const int tn  = (tid & 15) * 4;

    float acc[8][4];
    #pragma unroll
    for (int i = 0; i < 8; i++)
        #pragma unroll
        for (int j = 0; j < 4; j++) acc[i][j] = 0.f;

    for (int kk = 0; kk < K; kk += 16) {
        #pragma unroll
        for (int it = 0; it < 2; it++) {
            int t4 = it * 256 + tid;
            int row = t4 >> 2, col = (t4 & 3) * 4;
            float4 v = *reinterpret_cast<const float4*>(&A[(size_t)row * lda + kk + col]);
            As[col + 0][row] = v.x; As[col + 1][row] = v.y;
            As[col + 2][row] = v.z; As[col + 3][row] = v.w;
        }
        {
            int row = tid >> 4, c4 = (tid & 15) * 4;
            *reinterpret_cast<float4*>(&Bs[row][c4]) =
                *reinterpret_cast<const float4*>(&B[(size_t)(kk + row) * ldb + n0 + c4]);
        }
        __syncthreads();
        #pragma unroll
        for (int k = 0; k < 16; k++) {
            float ra[8], rb[4];
            *reinterpret_cast<float4*>(&ra[0]) = *reinterpret_cast<const float4*>(&As[k][tm]);
            *reinterpret_cast<float4*>(&ra[4]) = *reinterpret_cast<const float4*>(&As[k][tm + 4]);
            *reinterpret_cast<float4*>(&rb[0]) = *reinterpret_cast<const float4*>(&Bs[k][tn]);
            #pragma unroll
            for (int i = 0; i < 8; i++)
                #pragma unroll
                for (int j = 0; j < 4; j++)
                    acc[i][j] += ra[i] * rb[j];
        }
        __syncthreads();
    }
    #pragma unroll
    for (int j = 0; j < 4; j++) {
        float bv = bias ? bias[n0 + tn + j] : 0.f;
        #pragma unroll
        for (int i = 0; i < 8; i++)
            C[(size_t)(tm + i) * ldc + n0 + tn + j] = acc[i][j] + bv;
    }
}

__global__ __launch_bounds__(256)
void sgemm_bias_kernel(const float* __restrict__ A, int lda,
                       const float* __restrict__ B, int ldb,
                       float* __restrict__ C, int ldc,
                       const float* __restrict__ bias,
                       int K)
{
    sgemm_body(A, lda, B, ldb, C, ldc, bias, K, blockIdx.x * 64);
}

// both GRU projections in one launch: y=0 -> gin@Wk+bg, y=1 -> hidden@Wr
__global__ __launch_bounds__(256)
void sgemm_dual_kernel(const float* __restrict__ gin,
                       const float* __restrict__ hidden,
                       const float* __restrict__ Wk,
                       const float* __restrict__ Wr,
                       const float* __restrict__ bg,
                       float* __restrict__ xg,
                       float* __restrict__ hwr)
{
    if (blockIdx.y == 0)
        sgemm_body(gin,    GINLEN, Wk, G3U, xg,  G3U, bg,      GINLEN, blockIdx.x * 64);
    else
        sgemm_body(hidden, UNITS,  Wr, G3U, hwr, G3U, nullptr, UNITS,  blockIdx.x * 64);
}

// ======================= remaining pipeline =======================
// softmax fused with the fixed-order partial reduction
__global__ __launch_bounds__(256)
void softmax_kernel(const float* __restrict__ bV, float* __restrict__ out_attn)
{
    __shared__ float sh[SEQ];
    __shared__ float red[256];
    const int b = blockIdx.x, tid = threadIdx.x;
    const float bv = bV[0];

    float m = -1e30f;
    for (int i = tid; i < SEQ; i += 256) {
        size_t o = (size_t)b * SEQ + i;
        float s = bv;
        #pragma unroll
        for (int t = 0; t < NTILES; t++)
            s += g_part[(size_t)t * (BATCH * SEQ) + o];
        sh[i] = s;
        m = fmaxf(m, s);
    }
    red[tid] = m; __syncthreads();
    for (int s = 128; s > 0; s >>= 1) {
        if (tid < s) red[tid] = fmaxf(red[tid], red[tid + s]);
        __syncthreads();
    }
    m = red[0]; __syncthreads();

    float sum = 0.f;
    for (int i = tid; i < SEQ; i += 256) {
        float e = expf(sh[i] - m);
        sh[i] = e;
        sum += e;
    }
    red[tid] = sum; __syncthreads();
    for (int s = 128; s > 0; s >>= 1) {
        if (tid < s) red[tid] += red[tid + s];
        __syncthreads();
    }
    float inv = 1.f / red[0];
    for (int i = tid; i < SEQ; i += 256)
        out_attn[(size_t)b * SEQ + i] = sh[i] * inv;
}

__global__ __launch_bounds__(256)
void context_kernel(const float* __restrict__ enc, const float* __restrict__ attn)
{
    __shared__ float w[SEQ];
    const int b = blockIdx.y, u0 = blockIdx.x * 256, tid = threadIdx.x;

    for (int i = tid; i < SEQ; i += 256)
        w[i] = attn[(size_t)b * SEQ + i];
    __syncthreads();

    const float* e = enc + (size_t)b * SEQ * UNITS + u0 + tid;
    float acc = 0.f;
    #pragma unroll 8
    for (int s = 0; s < SEQ; s++)
        acc += w[s] * e[(size_t)s * UNITS];
    g_gin[(size_t)b * GINLEN + u0 + tid] = acc;
}

__global__ void copyx_kernel(const float* __restrict__ x)
{
    int i = blockIdx.x * 256 + threadIdx.x;
    if (i < BATCH * INDIM) {
        int b = i >> 6, u = i & 63;
        g_gin[(size_t)b * GINLEN + UNITS + u] = x[i];
    }
}

__global__ __launch_bounds__(256)
void gates_kernel(const float* __restrict__ hidden)
{
    int i = blockIdx.x * 256 + threadIdx.x;
    int b = i >> 10, u = i & 1023;
    size_t base = (size_t)b * G3U;
    float z = 1.f / (1.f + expf(-(g_xg[base + u] + g_hwr[base + u])));
    float r = 1.f / (1.f + expf(-(g_xg[base + UNITS + u] + g_hwr[base + UNITS + u])));
    g_z[i]  = z;
    g_rh[i] = r * hidden[i];
}

__global__ __launch_bounds__(256)
void state_kernel(const float* __restrict__ hidden, float* __restrict__ out_state)
{
    int i = blockIdx.x * 256 + threadIdx.x;
    int b = i >> 10, u = i & 1023;
    float hh = tanhf(g_xg[(size_t)b * G3U + 2 * UNITS + u] + g_rhwr[i]);
    float z  = g_z[i];
    float st = z * hidden[i] + (1.f - z) * hh;
    out_state[i] = st;
    g_state[i]   = st;
}

// ----------------------------------------------------------------------------
extern "C" void kernel_launch(void* const* d_in, const int* in_sizes, int n_in,
                              void* d_out_v, int out_size)
{
    const float* x      = (const float*)d_in[0];
    const float* hidden = (const float*)d_in[1];
    const float* enc    = (const float*)d_in[2];
    const float* W1     = (const float*)d_in[3];
    const float* b1     = (const float*)d_in[4];
    const float* W2     = (const float*)d_in[5];
    const float* b2     = (const float*)d_in[6];
    const float* V      = (const float*)d_in[7];
    const float* bV     = (const float*)d_in[8];
    const float* Wk     = (const float*)d_in[9];
    const float* Wr     = (const float*)d_in[10];
    const float* bg     = (const float*)d_in[11];
    const float* Wfc    = (const float*)d_in[12];
    const float* bfc    = (const float*)d_in[13];

    float* d_out     = (float*)d_out_v;
    float* out_fc    = d_out;
    float* out_state = d_out + BATCH * INDIM;
    float* out_attn  = d_out + BATCH * INDIM + BATCH * UNITS;

    float *q, *gin, *rh, *state, *xg, *hwr, *rhwr;
    cudaGetSymbolAddress((void**)&q,     g_q);
    cudaGetSymbolAddress((void**)&gin,   g_gin);
    cudaGetSymbolAddress((void**)&rh,    g_rh);
    cudaGetSymbolAddress((void**)&state, g_state);
    cudaGetSymbolAddress((void**)&xg,    g_xg);
    cudaGetSymbolAddress((void**)&hwr,   g_hwr);
    cudaGetSymbolAddress((void**)&rhwr,  g_rhwr);

    cudaFuncSetAttribute(score_mma_kernel,
                         cudaFuncAttributeMaxDynamicSharedMemorySize, SCORE_SMEM);

    // 1. precompute bf16 hi/lo operands
    split_enc_kernel<<<(int)(((size_t)BATCH * SEQ * UNITS) / (256 * 8)), 256>>>(enc);
    w1_split_kernel<<<dim3(32, 32), dim3(32, 8)>>>(W1);
    // 2. q = hidden @ W2 + b2
    sgemm_bias_kernel<<<dim3(UNITS / 64), 256>>>(hidden, UNITS, W2, UNITS, q, UNITS, b2, UNITS);
    // 3. tensor-core score GEMM + fused tanh/V epilogue (partials per n-tile)
    score_mma_kernel<<<dim3(NTILES, SEQ / 128, BATCH), 256, SCORE_SMEM>>>(q, b1, V);
    // 4. fused reduce + softmax -> attention weights (output slab 3)
    softmax_kernel<<<BATCH, 256>>>(bV, out_attn);
    // 5. gin = [context | x]
    copyx_kernel<<<(BATCH * INDIM + 255) / 256, 256>>>(x);
    context_kernel<<<dim3(UNITS / 256, BATCH), 256>>>(enc, out_attn);
    // 6. GRU projections (both in one launch)
    sgemm_dual_kernel<<<dim3(G3U / 64, 2), 256>>>(gin, hidden, Wk, Wr, bg, xg, hwr);
    // 7. gates
    gates_kernel<<<(BATCH * UNITS) / 256, 256>>>(hidden);
    // 8. (r*h) @ Wr_h
    sgemm_bias_kernel<<<dim3(UNITS / 64), 256>>>(rh, UNITS, Wr + 2 * UNITS, G3U, rhwr, UNITS, nullptr, UNITS);
    // 9. state (output slab 2)
    state_kernel<<<(BATCH * UNITS) / 256, 256>>>(hidden, out_state);
    // 10. out = state @ Wfc + bfc (output slab 1)
    sgemm_bias_kernel<<<dim3(INDIM / 64), 256>>>(state, UNITS, Wfc, INDIM, out_fc, INDIM, bfc, UNITS);
}

// round 8
// speedup vs baseline: 3.2237x; 1.2361x over previous
#include <cuda_runtime.h>
#include <cuda_bf16.h>
#include <cstdint>
#include <cstddef>

// ----------------------------------------------------------------------------
// Decoder step: Bahdanau attention + GRU cell + fc, B=128, S=1024, U=1024.
// R8: score GEMM on int8 mma.sync (m16n8k32, 2x bf16 rate) with 2-digit
// per-row quantization (3-term: A1B1 + (A1B0 + A0B1)/128), exact s32 accum.
// Expected rel_err ~1e-4 (<1e-3). Tail unchanged from R7.
// ----------------------------------------------------------------------------

#define BATCH   128
#define SEQ     1024
#define UNITS   1024
#define INDIM   64
#define GINLEN  (UNITS + INDIM)   // 1088
#define G3U     (3 * UNITS)       // 3072
#define NTILES  8                 // 1024 / 128 n-tiles

// ---------------- scratch (no allocations allowed) ----------------
__device__ __align__(16) int8_t g_enc_q1[(size_t)BATCH * SEQ * UNITS];  // 128MB
__device__ __align__(16) int8_t g_enc_q0[(size_t)BATCH * SEQ * UNITS];  // 128MB
__device__ __align__(16) int8_t g_w1t_q1[(size_t)UNITS * UNITS];        // W1^T
__device__ __align__(16) int8_t g_w1t_q0[(size_t)UNITS * UNITS];
__device__ __align__(16) float  g_sA    [BATCH * SEQ];
__device__ __align__(16) float  g_sB    [UNITS];
__device__ __align__(16) float  g_q     [BATCH * UNITS];
__device__ __align__(16) float  g_part  [NTILES * BATCH * SEQ];
__device__ __align__(16) float  g_gin   [BATCH * GINLEN];
__device__ __align__(16) float  g_xg    [BATCH * G3U];
__device__ __align__(16) float  g_hwr   [BATCH * G3U];
__device__ __align__(16) float  g_z     [BATCH * UNITS];
__device__ __align__(16) float  g_rh    [BATCH * UNITS];
__device__ __align__(16) float  g_rhwr  [BATCH * UNITS];
__device__ __align__(16) float  g_state [BATCH * UNITS];

// ======================= PTX helpers =======================
__device__ __forceinline__ uint32_t smem_u32(const void* p) {
    uint32_t a;
    asm("{ .reg .u64 t; cvta.to.shared.u64 t, %1; cvt.u32.u64 %0, t; }" : "=r"(a) : "l"(p));
    return a;
}
#define CP_ASYNC16(dst, src) \
    asm volatile("cp.async.cg.shared.global [%0], [%1], 16;" :: "r"(dst), "l"(src))
#define CP_COMMIT() asm volatile("cp.async.commit_group;" ::: "memory")

__device__ __forceinline__ void ldsm_x4(uint32_t r[4], uint32_t addr) {
    asm volatile("ldmatrix.sync.aligned.m8n8.x4.shared.b16 {%0,%1,%2,%3}, [%4];"
                 : "=r"(r[0]), "=r"(r[1]), "=r"(r[2]), "=r"(r[3]) : "r"(addr));
}
// s8 x s8 -> s32, m16n8k32
__device__ __forceinline__ void mma_s8(int c[4], const uint32_t a[4],
                                       uint32_t b0, uint32_t b1) {
    asm volatile(
        "mma.sync.aligned.m16n8k32.row.col.s32.s8.s8.s32 "
        "{%0,%1,%2,%3}, {%4,%5,%6,%7}, {%8,%9}, {%0,%1,%2,%3};"
        : "+r"(c[0]), "+r"(c[1]), "+r"(c[2]), "+r"(c[3])
        : "r"(a[0]), "r"(a[1]), "r"(a[2]), "r"(a[3]), "r"(b0), "r"(b1));
}

// ======================= quantization kernels =======================
// enc: per (b,s) row scale, 2-digit int8. 8 warps/block, 1 row/warp.
__global__ __launch_bounds__(256)
void quant_enc_kernel(const float* __restrict__ enc)
{
    const int warp = threadIdx.x >> 5, lane = threadIdx.x & 31;
    const size_t row = (size_t)blockIdx.x * 8 + warp;
    const float4* p4 = reinterpret_cast<const float4*>(enc + row * UNITS);

    float4 v[8];
    float mx = 0.f;
    #pragma unroll
    for (int i = 0; i < 8; i++) {
        v[i] = p4[lane + 32 * i];
        mx = fmaxf(mx, fmaxf(fmaxf(fabsf(v[i].x), fabsf(v[i].y)),
                             fmaxf(fabsf(v[i].z), fabsf(v[i].w))));
    }
    #pragma unroll
    for (int s = 16; s > 0; s >>= 1)
        mx = fmaxf(mx, __shfl_xor_sync(0xFFFFFFFF, mx, s));

    const float sinv = mx > 0.f ? 127.f / mx : 0.f;
    if (lane == 0) g_sA[row] = mx > 0.f ? mx / 127.f : 0.f;

    char4* q1 = reinterpret_cast<char4*>(g_enc_q1 + row * UNITS);
    char4* q0 = reinterpret_cast<char4*>(g_enc_q0 + row * UNITS);
    #pragma unroll
    for (int i = 0; i < 8; i++) {
        float a[4] = {v[i].x * sinv, v[i].y * sinv, v[i].z * sinv, v[i].w * sinv};
        char h[4], l[4];
        #pragma unroll
        for (int j = 0; j < 4; j++) {
            int hi = __float2int_rn(a[j]);
            int lo = __float2int_rn((a[j] - (float)hi) * 128.f);
            h[j] = (char)hi; l[j] = (char)lo;
        }
        q1[lane + 32 * i] = make_char4(h[0], h[1], h[2], h[3]);
        q0[lane + 32 * i] = make_char4(l[0], l[1], l[2], l[3]);
    }
}

// W1: per n-column scale; writes W1^T 2-digit int8. 1 thread per n.
__global__ __launch_bounds__(256)
void quant_w1_kernel(const float* __restrict__ W1)
{
    const int n = blockIdx.x * 256 + threadIdx.x;
    float mx = 0.f;
    for (int k = 0; k < UNITS; k++)
        mx = fmaxf(mx, fabsf(W1[(size_t)k * UNITS + n]));
    const float sinv = mx > 0.f ? 127.f / mx : 0.f;
    g_sB[n] = mx > 0.f ? mx / 127.f : 0.f;
    for (int k = 0; k < UNITS; k++) {
        float a = W1[(size_t)k * UNITS + n] * sinv;
        int hi = __float2int_rn(a);
        int lo = __float2int_rn((a - (float)hi) * 128.f);
        g_w1t_q1[(size_t)n * UNITS + k] = (int8_t)hi;
        g_w1t_q0[(size_t)n * UNITS + k] = (int8_t)lo;
    }
}

// ======================= int8 warp-MMA score GEMM =======================
// CTA: (b, s-tile 128, n-tile 128), 512 threads, warp grid 4x4 (tile 32x32).
// K = 1024 int8 in 16 chunks of 64 (64B rows). Stage: A1|A0|B1|B0, 8KB each,
// XOR swizzle c -> c ^ ((row>>1)&3). 3 stages = 96KB, single sync per chunk.
#define T_A1    0
#define T_A0    8192
#define T_B1    16384
#define T_B0    24576
#define STAGE_B 32768
#define NCHUNK  16
#define SCORE_SMEM (3 * STAGE_B)          // 98304

__device__ __forceinline__ void fill_stage(uint32_t stage,
                                           const char* a1, const char* a0,
                                           const char* b1, const char* b0,
                                           int chunk, int tid)
{
    const int kb  = chunk * 64;           // 64 int8 = 64 bytes
    const int row = tid >> 2, c = tid & 3;
    const uint32_t so = (uint32_t)(row * 64 + ((c ^ ((row >> 1) & 3)) << 4));
    const size_t   go = (size_t)row * UNITS + kb + c * 16;
    CP_ASYNC16(stage + T_A1 + so, a1 + go);
    CP_ASYNC16(stage + T_A0 + so, a0 + go);
    CP_ASYNC16(stage + T_B1 + so, b1 + go);
    CP_ASYNC16(stage + T_B0 + so, b0 + go);
}

__global__ __launch_bounds__(512, 1)
void score_mma_kernel(const float* __restrict__ q,
                      const float* __restrict__ b1v,
                      const float* __restrict__ V)
{
    extern __shared__ __align__(128) char smem[];
    __shared__ float sacc[128];
    const uint32_t sb = smem_u32(smem);

    const int tid    = threadIdx.x;
    const int lane   = tid & 31;
    const int wid    = tid >> 5;
    const int warp_m = wid >> 2;          // 0..3  (32 rows each)
    const int warp_n = wid & 3;           // 0..3  (32 cols each)
    const int n0     = blockIdx.x * 128;
    const int s0     = blockIdx.y * 128;
    const int b      = blockIdx.z;

    if (tid < 128) sacc[tid] = 0.f;

    const char* a1p = (const char*)(g_enc_q1 + ((size_t)b * SEQ + s0) * UNITS);
    const char* a0p = (const char*)(g_enc_q0 + ((size_t)b * SEQ + s0) * UNITS);
    const char* b1p = (const char*)(g_w1t_q1 + (size_t)n0 * UNITS);
    const char* b0p = (const char*)(g_w1t_q0 + (size_t)n0 * UNITS);

    fill_stage(sb,           a1p, a0p, b1p, b0p, 0, tid); CP_COMMIT();
    fill_stage(sb + STAGE_B, a1p, a0p, b1p, b0p, 1, tid); CP_COMMIT();

    int acc1[2][4][4], accm[2][4][4];
    #pragma unroll
    for (int mi = 0; mi < 2; mi++)
        #pragma unroll
        for (int ni = 0; ni < 4; ni++)
            #pragma unroll
            for (int c = 0; c < 4; c++) { acc1[mi][ni][c] = 0; accm[mi][ni][c] = 0; }

    // ldmatrix lane addressing (A and B symmetric):
    // row = base + (lane&7) + ((lane>>3)&1)*8 ; 16B-col within k32 = lane>>4
    uint32_t a_off[2], xa[2], b_off[2], xb[2];
    #pragma unroll
    for (int mi = 0; mi < 2; mi++) {
        int row = warp_m * 32 + mi * 16 + (lane & 7) + ((lane >> 3) & 1) * 8;
        a_off[mi] = (uint32_t)row * 64;
        xa[mi]    = (uint32_t)((row >> 1) & 3);
    }
    #pragma unroll
    for (int p = 0; p < 2; p++) {
        int row = warp_n * 32 + p * 16 + (lane & 7) + ((lane >> 3) & 1) * 8;
        b_off[p] = (uint32_t)row * 64;
        xb[p]    = (uint32_t)((row >> 1) & 3);
    }
    const uint32_t ch = (uint32_t)(lane >> 4);   // k16-half selector

    #pragma unroll 1
    for (int c = 0; c < NCHUNK; c++) {
        if (c >= NCHUNK - 1) asm volatile("cp.async.wait_group 0;" ::: "memory");
        else                 asm volatile("cp.async.wait_group 1;" ::: "memory");
        __syncthreads();   // chunk c visible; iteration c-1 MMAs done everywhere

        const uint32_t slot = sb + (uint32_t)(c % 3) * STAGE_B;

        if (c + 2 < NCHUNK) {   // slot (c+2)%3 was consumed at iter c-1
            fill_stage(sb + (uint32_t)((c + 2) % 3) * STAGE_B,
                       a1p, a0p, b1p, b0p, c + 2, tid);
            CP_COMMIT();
        }

        #pragma unroll
        for (int j = 0; j < 2; j++) {     // two k32 steps per 64-chunk
            const uint32_t cj = (uint32_t)(j * 2) + ch;
            uint32_t bf1[2][4], bf0[2][4];
            #pragma unroll
            for (int p = 0; p < 2; p++) {
                uint32_t ad = slot + T_B1 + b_off[p] + ((cj ^ xb[p]) << 4);
                ldsm_x4(bf1[p], ad);
                ldsm_x4(bf0[p], ad + (T_B0 - T_B1));
            }
            #pragma unroll
            for (int mi = 0; mi < 2; mi++) {
                uint32_t ad = slot + T_A1 + a_off[mi] + ((cj ^ xa[mi]) << 4);
                uint32_t af1[4], af0[4];
                ldsm_x4(af1, ad);
                ldsm_x4(af0, ad + (T_A0 - T_A1));
                #pragma unroll
                for (int ni = 0; ni < 4; ni++) {
                    const int p = ni >> 1, h = ni & 1;
                    uint32_t bh0 = bf1[p][h], bh1 = bf1[p][h + 2]; // B1 k-lo/k-hi
                    uint32_t bl0 = bf0[p][h], bl1 = bf0[p][h + 2]; // B0
                    mma_s8(acc1[mi][ni], af1, bh0, bh1);           // A1*B1
                    mma_s8(accm[mi][ni], af1, bl0, bl1);           // A1*B0
                    mma_s8(accm[mi][ni], af0, bh0, bh1);           // A0*B1
                }
            }
        }
    }

    // Epilogue: val = sA*sB*(acc1 + accm/128); part[s] = sum_n V*tanh(val+q+b1)
    const size_t qb = (size_t)b * UNITS;
    const float* sArow = g_sA + (size_t)b * SEQ + s0;
    #pragma unroll
    for (int mi = 0; mi < 2; mi++) {
        float p0 = 0.f, p1 = 0.f;
        const int r   = warp_m * 32 + mi * 16 + (lane >> 2);
        const float sa0 = sArow[r], sa1 = sArow[r + 8];
        #pragma unroll
        for (int ni = 0; ni < 4; ni++) {
            #pragma unroll
            for (int cc = 0; cc < 4; cc++) {
                int n = n0 + warp_n * 32 + ni * 8 + (lane & 3) * 2 + (cc & 1);
                float sa  = (cc < 2) ? sa0 : sa1;
                float val = sa * g_sB[n] *
                            ((float)acc1[mi][ni][cc] + (float)accm[mi][ni][cc] * 0.0078125f);
                float t = V[n] * tanhf(val + q[qb + n] + b1v[n]);
                if (cc < 2) p0 += t; else p1 += t;
            }
        }
        p0 += __shfl_xor_sync(0xFFFFFFFF, p0, 1);
        p0 += __shfl_xor_sync(0xFFFFFFFF, p0, 2);
        p1 += __shfl_xor_sync(0xFFFFFFFF, p1, 1);
        p1 += __shfl_xor_sync(0xFFFFFFFF, p1, 2);
        if ((lane & 3) == 0) {
            atomicAdd(&sacc[r],     p0);
            atomicAdd(&sacc[r + 8], p1);
        }
    }
    __syncthreads();
    if (tid < 128)
        g_part[(size_t)blockIdx.x * (BATCH * SEQ) + (size_t)b * SEQ + s0 + tid] = sacc[tid];
}

// ======================= fp32 SGEMM (small GEMMs) =======================
__device__ __forceinline__
void sgemm_body(const float* __restrict__ A, int lda,
                const float* __restrict__ B, int ldb,
                float* __restrict__ C, int ldc,
                const float* __restrict__ bias,
                int K, int n0)
{
    __shared__ float As[16][128 + 4];
    __shared__ float Bs[16][64];

    const int tid = threadIdx.x;
    const int tm  = (tid >> 4) * 8;
    const int tn  = (tid & 15) * 4;

    float acc[8][4];
    #pragma unroll
    for (int i = 0; i < 8; i++)
        #pragma unroll
        for (int j = 0; j < 4; j++) acc[i][j] = 0.f;

    for (int kk = 0; kk < K; kk += 16) {
        #pragma unroll
        for (int it = 0; it < 2; it++) {
            int t4 = it * 256 + tid;
            int row = t4 >> 2, col = (t4 & 3) * 4;
            float4 v = *reinterpret_cast<const float4*>(&A[(size_t)row * lda + kk + col]);
            As[col + 0][row] = v.x; As[col + 1][row] = v.y;
            As[col + 2][row] = v.z; As[col + 3][row] = v.w;
        }
        {
            int row = tid >> 4, c4 = (tid & 15) * 4;
            *reinterpret_cast<float4*>(&Bs[row][c4]) =
                *reinterpret_cast<const float4*>(&B[(size_t)(kk + row) * ldb + n0 + c4]);
        }
        __syncthreads();
        #pragma unroll
        for (int k = 0; k < 16; k++) {
            float ra[8], rb[4];
            *reinterpret_cast<float4*>(&ra[0]) = *reinterpret_cast<const float4*>(&As[k][tm]);
            *reinterpret_cast<float4*>(&ra[4]) = *reinterpret_cast<const float4*>(&As[k][tm + 4]);
            *reinterpret_cast<float4*>(&rb[0]) = *reinterpret_cast<const float4*>(&Bs[k][tn]);
            #pragma unroll
            for (int i = 0; i < 8; i++)
                #pragma unroll
                for (int j = 0; j < 4; j++)
                    acc[i][j] += ra[i] * rb[j];
        }
        __syncthreads();
    }
    #pragma unroll
    for (int j = 0; j < 4; j++) {
        float bv = bias ? bias[n0 + tn + j] : 0.f;
        #pragma unroll
        for (int i = 0; i < 8; i++)
            C[(size_t)(tm + i) * ldc + n0 + tn + j] = acc[i][j] + bv;
    }
}

__global__ __launch_bounds__(256)
void sgemm_bias_kernel(const float* __restrict__ A, int lda,
                       const float* __restrict__ B, int ldb,
                       float* __restrict__ C, int ldc,
                       const float* __restrict__ bias,
                       int K)
{
    sgemm_body(A, lda, B, ldb, C, ldc, bias, K, blockIdx.x * 64);
}

__global__ __launch_bounds__(256)
void sgemm_dual_kernel(const float* __restrict__ gin,
                       const float* __restrict__ hidden,
                       const float* __restrict__ Wk,
                       const float* __restrict__ Wr,
                       const float* __restrict__ bg,
                       float* __restrict__ xg,
                       float* __restrict__ hwr)
{
    if (blockIdx.y == 0)
        sgemm_body(gin,    GINLEN, Wk, G3U, xg,  G3U, bg,      GINLEN, blockIdx.x * 64);
    else
        sgemm_body(hidden, UNITS,  Wr, G3U, hwr, G3U, nullptr, UNITS,  blockIdx.x * 64);
}

// ======================= remaining pipeline =======================
__global__ __launch_bounds__(256)
void softmax_kernel(const float* __restrict__ bV, float* __restrict__ out_attn)
{
    __shared__ float sh[SEQ];
    __shared__ float red[256];
    const int b = blockIdx.x, tid = threadIdx.x;
    const float bv = bV[0];

    float m = -1e30f;
    for (int i = tid; i < SEQ; i += 256) {
        size_t o = (size_t)b * SEQ + i;
        float s = bv;
        #pragma unroll
        for (int t = 0; t < NTILES; t++)
            s += g_part[(size_t)t * (BATCH * SEQ) + o];
        sh[i] = s;
        m = fmaxf(m, s);
    }
    red[tid] = m; __syncthreads();
    for (int s = 128; s > 0; s >>= 1) {
        if (tid < s) red[tid] = fmaxf(red[tid], red[tid + s]);
        __syncthreads();
    }
    m = red[0]; __syncthreads();

    float sum = 0.f;
    for (int i = tid; i < SEQ; i += 256) {
        float e = expf(sh[i] - m);
        sh[i] = e;
        sum += e;
    }
    red[tid] = sum; __syncthreads();
    for (int s = 128; s > 0; s >>= 1) {
        if (tid < s) red[tid] += red[tid + s];
        __syncthreads();
    }
    float inv = 1.f / red[0];
    for (int i = tid; i < SEQ; i += 256)
        out_attn[(size_t)b * SEQ + i] = sh[i] * inv;
}

__global__ __launch_bounds__(256)
void context_kernel(const float* __restrict__ enc, const float* __restrict__ attn)
{
    __shared__ float w[SEQ];
    const int b = blockIdx.y, u0 = blockIdx.x * 256, tid = threadIdx.x;

    for (int i = tid; i < SEQ; i += 256)
        w[i] = attn[(size_t)b * SEQ + i];
    __syncthreads();

    const float* e = enc + (size_t)b * SEQ * UNITS + u0 + tid;
    float acc = 0.f;
    #pragma unroll 8
    for (int s = 0; s < SEQ; s++)
        acc += w[s] * e[(size_t)s * UNITS];
    g_gin[(size_t)b * GINLEN + u0 + tid] = acc;
}

__global__ void copyx_kernel(const float* __restrict__ x)
{
    int i = blockIdx.x * 256 + threadIdx.x;
    if (i < BATCH * INDIM) {
        int b = i >> 6, u = i & 63;
        g_gin[(size_t)b * GINLEN + UNITS + u] = x[i];
    }
}

__global__ __launch_bounds__(256)
void gates_kernel(const float* __restrict__ hidden)
{
    int i = blockIdx.x * 256 + threadIdx.x;
    int b = i >> 10, u = i & 1023;
    size_t base = (size_t)b * G3U;
    float z = 1.f / (1.f + expf(-(g_xg[base + u] + g_hwr[base + u])));
    float r = 1.f / (1.f + expf(-(g_xg[base + UNITS + u] + g_hwr[base + UNITS + u])));
    g_z[i]  = z;
    g_rh[i] = r * hidden[i];
}

__global__ __launch_bounds__(256)
void state_kernel(const float* __restrict__ hidden, float* __restrict__ out_state)
{
    int i = blockIdx.x * 256 + threadIdx.x;
    int b = i >> 10, u = i & 1023;
    float hh = tanhf(g_xg[(size_t)b * G3U + 2 * UNITS + u] + g_rhwr[i]);
    float z  = g_z[i];
    float st = z * hidden[i] + (1.f - z) * hh;
    out_state[i] = st;
    g_state[i]   = st;
}

// ----------------------------------------------------------------------------
extern "C" void kernel_launch(void* const* d_in, const int* in_sizes, int n_in,
                              void* d_out_v, int out_size)
{
    const float* x      = (const float*)d_in[0];
    const float* hidden = (const float*)d_in[1];
    const float* enc    = (const float*)d_in[2];
    const float* W1     = (const float*)d_in[3];
    const float* b1     = (const float*)d_in[4];
    const float* W2     = (const float*)d_in[5];
    const float* b2     = (const float*)d_in[6];
    const float* V      = (const float*)d_in[7];
    const float* bV     = (const float*)d_in[8];
    const float* Wk     = (const float*)d_in[9];
    const float* Wr     = (const float*)d_in[10];
    const float* bg     = (const float*)d_in[11];
    const float* Wfc    = (const float*)d_in[12];
    const float* bfc    = (const float*)d_in[13];

    float* d_out     = (float*)d_out_v;
    float* out_fc    = d_out;
    float* out_state = d_out + BATCH * INDIM;
    float* out_attn  = d_out + BATCH * INDIM + BATCH * UNITS;

    float *q, *gin, *rh, *state, *xg, *hwr, *rhwr;
    cudaGetSymbolAddress((void**)&q,     g_q);
    cudaGetSymbolAddress((void**)&gin,   g_gin);
    cudaGetSymbolAddress((void**)&rh,    g_rh);
    cudaGetSymbolAddress((void**)&state, g_state);
    cudaGetSymbolAddress((void**)&xg,    g_xg);
    cudaGetSymbolAddress((void**)&hwr,   g_hwr);
    cudaGetSymbolAddress((void**)&rhwr,  g_rhwr);

    cudaFuncSetAttribute(score_mma_kernel,
                         cudaFuncAttributeMaxDynamicSharedMemorySize, SCORE_SMEM);

    // 1. quantize operands (2-digit int8, per-row scales)
    quant_enc_kernel<<<(BATCH * SEQ) / 8, 256>>>(enc);
    quant_w1_kernel<<<UNITS / 256, 256>>>(W1);
    // 2. q = hidden @ W2 + b2
    sgemm_bias_kernel<<<dim3(UNITS / 64), 256>>>(hidden, UNITS, W2, UNITS, q, UNITS, b2, UNITS);
    // 3. int8 tensor-core score GEMM + fused tanh/V epilogue
    score_mma_kernel<<<dim3(NTILES, SEQ / 128, BATCH), 512, SCORE_SMEM>>>(q, b1, V);
    // 4. fused reduce + softmax -> attention weights (output slab 3)
    softmax_kernel<<<BATCH, 256>>>(bV, out_attn);
    // 5. gin = [context | x]
    copyx_kernel<<<(BATCH * INDIM + 255) / 256, 256>>>(x);
    context_kernel<<<dim3(UNITS / 256, BATCH), 256>>>(enc, out_attn);
    // 6. GRU projections (both in one launch)
    sgemm_dual_kernel<<<dim3(G3U / 64, 2), 256>>>(gin, hidden, Wk, Wr, bg, xg, hwr);
    // 7. gates
    gates_kernel<<<(BATCH * UNITS) / 256, 256>>>(hidden);
    // 8. (r*h) @ Wr_h
    sgemm_bias_kernel<<<dim3(UNITS / 64), 256>>>(rh, UNITS, Wr + 2 * UNITS, G3U, rhwr, UNITS, nullptr, UNITS);
    // 9. state (output slab 2)
    state_kernel<<<(BATCH * UNITS) / 256, 256>>>(hidden, out_state);
    // 10. out = state @ Wfc + bfc (output slab 1)
    sgemm_bias_kernel<<<dim3(INDIM / 64), 256>>>(state, UNITS, Wfc, INDIM, out_fc, INDIM, bfc, UNITS);
}